// round 1
// baseline (speedup 1.0000x reference)
#include <cuda_runtime.h>

#define NG      4096
#define OUTD    64
#define HID     128
#define NFEAT   125
#define MT      64      // nodes per block tile
#define LDA     132     // padded smem row stride (floats)
#define NTHREADS 256

__device__ float g_accum[NG * OUTD];
__device__ float g_cnt[NG];

__global__ void zero_kernel() {
    int idx = blockIdx.x * blockDim.x + threadIdx.x;
    if (idx < NG * OUTD) g_accum[idx] = 0.0f;
    if (idx < NG)        g_cnt[idx]   = 0.0f;
}

// C[MT, ncols] = act(A[MT, HID] @ W[HID, ncols] + b)
// A, C in smem (stride LDA). W staged into smem from global. 256 threads.
__device__ __forceinline__ void gemm_layer(
    const float* __restrict__ Ain, float* __restrict__ Cout,
    float* Ws, float* bs,
    const float* __restrict__ Wg, const float* __restrict__ bg,
    int ncols, bool do_relu, int tid)
{
    // stage W (vectorized) and bias
    int nc4 = ncols >> 2;
    for (int idx = tid; idx < HID * nc4; idx += NTHREADS) {
        int r  = idx / nc4;
        int c4 = idx - r * nc4;
        *reinterpret_cast<float4*>(&Ws[r * LDA + c4 * 4]) =
            reinterpret_cast<const float4*>(Wg)[idx];
    }
    if (tid < ncols) bs[tid] = bg[tid];
    __syncthreads();

    int tx = tid & 15;      // column group (8 cols each)
    int ty = tid >> 4;      // row group (4 rows each)
    int col0 = tx * 8;

    if (col0 < ncols) {
        float acc[4][8];
        #pragma unroll
        for (int i = 0; i < 4; i++)
            #pragma unroll
            for (int j = 0; j < 8; j++)
                acc[i][j] = bs[col0 + j];

        #pragma unroll 4
        for (int k = 0; k < HID; k++) {
            float4 w0 = *reinterpret_cast<const float4*>(&Ws[k * LDA + col0]);
            float4 w1 = *reinterpret_cast<const float4*>(&Ws[k * LDA + col0 + 4]);
            float wv[8] = {w0.x, w0.y, w0.z, w0.w, w1.x, w1.y, w1.z, w1.w};
            #pragma unroll
            for (int i = 0; i < 4; i++) {
                float a = Ain[(ty * 4 + i) * LDA + k];
                #pragma unroll
                for (int j = 0; j < 8; j++)
                    acc[i][j] = fmaf(a, wv[j], acc[i][j]);
            }
        }

        #pragma unroll
        for (int i = 0; i < 4; i++) {
            #pragma unroll
            for (int j = 0; j < 8; j++) {
                float v = acc[i][j];
                if (do_relu) v = fmaxf(v, 0.0f);
                Cout[(ty * 4 + i) * LDA + col0 + j] = v;
            }
        }
    }
    __syncthreads();
}

__global__ void __launch_bounds__(NTHREADS, 1) gnn_kernel(
    const float* __restrict__ pos, const int* __restrict__ z,
    const int* __restrict__ batch, const float* __restrict__ emb,
    const float* __restrict__ W1, const float* __restrict__ b1,
    const float* __restrict__ W2, const float* __restrict__ b2,
    const float* __restrict__ W3, const float* __restrict__ b3,
    int N)
{
    extern __shared__ float smem[];
    float* As = smem;                    // MT*LDA
    float* Cs = As + MT * LDA;           // MT*LDA
    float* Ws = Cs + MT * LDA;           // HID*LDA
    float* bs = Ws + HID * LDA;          // HID
    int*   sb = (int*)(bs + HID);        // MT (batch ids)
    int*   sz = sb + MT;                 // MT (type ids)

    int tid = threadIdx.x;
    int node0 = blockIdx.x * MT;

    if (tid < MT) {
        int node = node0 + tid;
        sb[tid] = (node < N) ? batch[node] : -1;
        sz[tid] = (node < N) ? z[node]     : 0;
    }
    __syncthreads();

    // gather x = [pos(3) | emb[z](125)] into As
    for (int idx = tid; idx < MT * HID; idx += NTHREADS) {
        int i = idx >> 7;
        int c = idx & 127;
        int node = node0 + i;
        float v = 0.0f;
        if (node < N)
            v = (c < 3) ? pos[node * 3 + c] : emb[sz[i] * NFEAT + (c - 3)];
        As[i * LDA + c] = v;
    }
    __syncthreads();

    gemm_layer(As, Cs, Ws, bs, W1, b1, HID,  true,  tid);   // x  -> h1
    gemm_layer(Cs, As, Ws, bs, W2, b2, HID,  true,  tid);   // h1 -> h2
    gemm_layer(As, Cs, Ws, bs, W3, b3, OUTD, false, tid);   // h2 -> y

    // segment reduce within tile (batch is sorted): one thread per output col
    if (tid < OUTD) {
        float sum = 0.0f;
        int cur = -1;
        for (int i = 0; i < MT; i++) {
            int b = sb[i];
            if (b != cur) {
                if (cur >= 0) atomicAdd(&g_accum[cur * OUTD + tid], sum);
                sum = 0.0f;
                cur = b;
            }
            if (b >= 0) sum += Cs[i * LDA + tid];
        }
        if (cur >= 0) atomicAdd(&g_accum[cur * OUTD + tid], sum);
    } else if (tid == OUTD) {
        // per-graph counts
        float cntv = 0.0f;
        int cur = -1;
        for (int i = 0; i < MT; i++) {
            int b = sb[i];
            if (b != cur) {
                if (cur >= 0) atomicAdd(&g_cnt[cur], cntv);
                cntv = 0.0f;
                cur = b;
            }
            if (b >= 0) cntv += 1.0f;
        }
        if (cur >= 0) atomicAdd(&g_cnt[cur], cntv);
    }
}

__global__ void finalize_kernel(float* __restrict__ out) {
    int idx = blockIdx.x * blockDim.x + threadIdx.x;
    if (idx < NG * OUTD)
        out[idx] = g_accum[idx] / fmaxf(g_cnt[idx >> 6], 1.0f);
}

extern "C" void kernel_launch(void* const* d_in, const int* in_sizes, int n_in,
                              void* d_out, int out_size)
{
    const float* pos   = (const float*)d_in[0];
    const int*   z     = (const int*)  d_in[1];
    const int*   batch = (const int*)  d_in[2];
    const float* emb   = (const float*)d_in[3];
    const float* W1    = (const float*)d_in[4];
    const float* b1    = (const float*)d_in[5];
    const float* W2    = (const float*)d_in[6];
    const float* b2    = (const float*)d_in[7];
    const float* W3    = (const float*)d_in[8];
    const float* b3    = (const float*)d_in[9];

    int N = in_sizes[1];   // z count = number of nodes

    size_t smem_bytes = (size_t)(MT * LDA * 2 + HID * LDA + HID) * sizeof(float)
                      + (size_t)(MT * 2) * sizeof(int);

    cudaFuncSetAttribute(gnn_kernel, cudaFuncAttributeMaxDynamicSharedMemorySize,
                         (int)smem_bytes);

    zero_kernel<<<(NG * OUTD + 255) / 256, 256>>>();

    int blocks = (N + MT - 1) / MT;
    gnn_kernel<<<blocks, NTHREADS, smem_bytes>>>(pos, z, batch, emb,
                                                 W1, b1, W2, b2, W3, b3, N);

    finalize_kernel<<<(NG * OUTD + 255) / 256, 256>>>((float*)d_out);
}

// round 7
// speedup vs baseline: 1.4683x; 1.4683x over previous
#include <cuda_runtime.h>

#define NG      4096
#define OUTD    64
#define HID     128
#define NFEAT   125
#define NTYPES  100
#define MT      64
#define LDA     132
#define NTHREADS 256

__device__ float g_accum[NG * OUTD];
__device__ float g_cnt[NG];
__device__ float g_E1[NTYPES * HID];

// E1[t][c] = b1[c] + sum_d emb[t][d] * W1[3+d][c]   (exact fp32)
__global__ void e1_kernel(const float* __restrict__ emb,
                          const float* __restrict__ W1,
                          const float* __restrict__ b1) {
    __shared__ float e[NFEAT];
    int t = blockIdx.x, c = threadIdx.x;
    if (c < NFEAT) e[c] = emb[t * NFEAT + c];
    __syncthreads();
    float s = b1[c];
#pragma unroll 5
    for (int d = 0; d < NFEAT; d++)
        s = fmaf(e[d], W1[(3 + d) * HID + c], s);
    g_E1[t * HID + c] = s;
}

__global__ void zero_kernel() {
    int idx = blockIdx.x * blockDim.x + threadIdx.x;
    if (idx < NG * OUTD) g_accum[idx] = 0.0f;
    if (idx < NG)        g_cnt[idx]   = 0.0f;
}

// R1's known-good fp32 SIMT layer: C[MT,ncols] = act(A[MT,HID] @ W + b)
__device__ __forceinline__ void gemm_layer(
    const float* __restrict__ Ain, float* __restrict__ Cout,
    float* Ws, float* bs,
    const float* __restrict__ Wg, const float* __restrict__ bg,
    int ncols, bool do_relu, int tid)
{
    int nc4 = ncols >> 2;
    for (int idx = tid; idx < HID * nc4; idx += NTHREADS) {
        int r  = idx / nc4;
        int c4 = idx - r * nc4;
        *reinterpret_cast<float4*>(&Ws[r * LDA + c4 * 4]) =
            reinterpret_cast<const float4*>(Wg)[idx];
    }
    if (tid < ncols) bs[tid] = bg[tid];
    __syncthreads();

    int tx = tid & 15;
    int ty = tid >> 4;
    int col0 = tx * 8;

    if (col0 < ncols) {
        float acc[4][8];
        #pragma unroll
        for (int i = 0; i < 4; i++)
            #pragma unroll
            for (int j = 0; j < 8; j++)
                acc[i][j] = bs[col0 + j];

        #pragma unroll 4
        for (int k = 0; k < HID; k++) {
            float4 w0 = *reinterpret_cast<const float4*>(&Ws[k * LDA + col0]);
            float4 w1 = *reinterpret_cast<const float4*>(&Ws[k * LDA + col0 + 4]);
            float wv[8] = {w0.x, w0.y, w0.z, w0.w, w1.x, w1.y, w1.z, w1.w};
            #pragma unroll
            for (int i = 0; i < 4; i++) {
                float a = Ain[(ty * 4 + i) * LDA + k];
                #pragma unroll
                for (int j = 0; j < 8; j++)
                    acc[i][j] = fmaf(a, wv[j], acc[i][j]);
            }
        }

        #pragma unroll
        for (int i = 0; i < 4; i++) {
            #pragma unroll
            for (int j = 0; j < 8; j++) {
                float v = acc[i][j];
                if (do_relu) v = fmaxf(v, 0.0f);
                Cout[(ty * 4 + i) * LDA + col0 + j] = v;
            }
        }
    }
    __syncthreads();
}

__global__ void __launch_bounds__(NTHREADS, 1) gnn_kernel(
    const float* __restrict__ pos, const int* __restrict__ z,
    const int* __restrict__ batch, const float* __restrict__ W1,
    const float* __restrict__ W2, const float* __restrict__ b2,
    const float* __restrict__ W3, const float* __restrict__ b3,
    int N)
{
    extern __shared__ float smem[];
    float* As = smem;                    // MT*LDA
    float* Cs = As + MT * LDA;           // MT*LDA
    float* Ws = Cs + MT * LDA;           // HID*LDA
    float* bs = Ws + HID * LDA;          // HID
    int*   sb = (int*)(bs + HID);        // MT (batch ids)
    int*   sz = sb + MT;                 // MT (type ids)

    int tid = threadIdx.x;
    int node0 = blockIdx.x * MT;

    if (tid < MT) {
        int node = node0 + tid;
        sb[tid] = (node < N) ? batch[node] : -1;
        sz[tid] = (node < N) ? z[node]     : 0;
    }
    __syncthreads();

    // layer 1 (THE ONLY CHANGE vs R1): h1 = relu(E1[z] + pos @ W1[0:3])
    // pos and W1 rows 0..2 read directly from global (L1/L2 cached).
    for (int idx = tid; idx < MT * HID; idx += NTHREADS) {
        int i = idx >> 7;
        int c = idx & 127;
        int node = node0 + i;
        float v = 0.0f;
        if (node < N) {
            v = g_E1[sz[i] * HID + c];
            v = fmaf(pos[node * 3 + 0], W1[c],       v);
            v = fmaf(pos[node * 3 + 1], W1[128 + c], v);
            v = fmaf(pos[node * 3 + 2], W1[256 + c], v);
            v = fmaxf(v, 0.0f);
        }
        As[i * LDA + c] = v;
    }
    __syncthreads();

    gemm_layer(As, Cs, Ws, bs, W2, b2, HID,  true,  tid);   // h1 -> h2
    gemm_layer(Cs, As, Ws, bs, W3, b3, OUTD, false, tid);   // h2 -> y (in As)

    // R1's exact segment reduction (batch sorted): one thread per output col
    if (tid < OUTD) {
        float sum = 0.0f;
        int cur = -1;
        for (int i = 0; i < MT; i++) {
            int b = sb[i];
            if (b != cur) {
                if (cur >= 0) atomicAdd(&g_accum[cur * OUTD + tid], sum);
                sum = 0.0f;
                cur = b;
            }
            if (b >= 0) sum += As[i * LDA + tid];
        }
        if (cur >= 0) atomicAdd(&g_accum[cur * OUTD + tid], sum);
    } else if (tid == OUTD) {
        float cntv = 0.0f;
        int cur = -1;
        for (int i = 0; i < MT; i++) {
            int b = sb[i];
            if (b != cur) {
                if (cur >= 0) atomicAdd(&g_cnt[cur], cntv);
                cntv = 0.0f;
                cur = b;
            }
            if (b >= 0) cntv += 1.0f;
        }
        if (cur >= 0) atomicAdd(&g_cnt[cur], cntv);
    }
}

__global__ void finalize_kernel(float* __restrict__ out) {
    int idx = blockIdx.x * blockDim.x + threadIdx.x;
    if (idx < NG * OUTD)
        out[idx] = g_accum[idx] / fmaxf(g_cnt[idx >> 6], 1.0f);
}

extern "C" void kernel_launch(void* const* d_in, const int* in_sizes, int n_in,
                              void* d_out, int out_size)
{
    const float* pos   = (const float*)d_in[0];
    const int*   z     = (const int*)  d_in[1];
    const int*   batch = (const int*)  d_in[2];
    const float* emb   = (const float*)d_in[3];
    const float* W1    = (const float*)d_in[4];
    const float* b1    = (const float*)d_in[5];
    const float* W2    = (const float*)d_in[6];
    const float* b2    = (const float*)d_in[7];
    const float* W3    = (const float*)d_in[8];
    const float* b3    = (const float*)d_in[9];

    int N = in_sizes[1];   // z count = number of nodes

    size_t smem_bytes = (size_t)(MT * LDA * 2 + HID * LDA + HID) * sizeof(float)
                      + (size_t)(MT * 2) * sizeof(int);

    cudaFuncSetAttribute(gnn_kernel, cudaFuncAttributeMaxDynamicSharedMemorySize,
                         (int)smem_bytes);

    e1_kernel<<<NTYPES, HID>>>(emb, W1, b1);
    zero_kernel<<<(NG * OUTD + 255) / 256, 256>>>();

    int blocks = (N + MT - 1) / MT;
    gnn_kernel<<<blocks, NTHREADS, smem_bytes>>>(pos, z, batch, W1,
                                                 W2, b2, W3, b3, N);

    finalize_kernel<<<(NG * OUTD + 255) / 256, 256>>>((float*)d_out);
}

// round 8
// speedup vs baseline: 4.2566x; 2.8989x over previous
#include <cuda_runtime.h>
#include <cuda_bf16.h>

#define NG      4096
#define OUTD    64
#define HID     128
#define NFEAT   125
#define NTYPES  100
#define MT      128
#define LDA     132
#define NTHREADS 256
#define KB16    8
#define NB2     16
#define NB3     8
#define WSTR2   36
#define WSTR3   20

__device__ float    g_accum[NG * OUTD];
__device__ float    g_cnt[NG];
__device__ float    g_E1[NTYPES * HID];
__device__ unsigned g_Whi2[KB16 * 32 * WSTR2];
__device__ unsigned g_Wlo2[KB16 * 32 * WSTR2];
__device__ unsigned g_Whi3[KB16 * 32 * WSTR3];
__device__ unsigned g_Wlo3[KB16 * 32 * WSTR3];

__device__ __forceinline__ void bf16_split(float f, unsigned short& h, unsigned short& l) {
    __nv_bfloat16 hb = __float2bfloat16(f);
    __nv_bfloat16 lb = __float2bfloat16(f - __bfloat162float(hb));
    h = __bfloat16_as_ushort(hb);
    l = __bfloat16_as_ushort(lb);
}
__device__ __forceinline__ unsigned pk(unsigned short e0, unsigned short e1) {
    return (unsigned)e0 | ((unsigned)e1 << 16);
}

#define MMA_BF16(c, a0, a1, a2, a3, b0, b1)                                   \
    asm volatile("mma.sync.aligned.m16n8k16.row.col.f32.bf16.bf16.f32 "       \
                 "{%0,%1,%2,%3},{%4,%5,%6,%7},{%8,%9},{%0,%1,%2,%3};"         \
                 : "+f"(c[0]), "+f"(c[1]), "+f"(c[2]), "+f"(c[3])             \
                 : "r"(a0), "r"(a1), "r"(a2), "r"(a3), "r"(b0), "r"(b1))

__global__ void e1_kernel(const float* __restrict__ emb,
                          const float* __restrict__ W1,
                          const float* __restrict__ b1) {
    __shared__ float e[NFEAT];
    int t = blockIdx.x, c = threadIdx.x;
    if (c < NFEAT) e[c] = emb[t * NFEAT + c];
    __syncthreads();
    float s = b1[c];
#pragma unroll 5
    for (int d = 0; d < NFEAT; d++)
        s = fmaf(e[d], W1[(3 + d) * HID + c], s);
    g_E1[t * HID + c] = s;
}

__global__ void zero_kernel() {
    int idx = blockIdx.x * blockDim.x + threadIdx.x;
    if (idx < NG * OUTD) g_accum[idx] = 0.0f;
    if (idx < NG)        g_cnt[idx]   = 0.0f;
}

__global__ void permute_w_kernel(const float* __restrict__ W2,
                                 const float* __restrict__ W3) {
    int idx = blockIdx.x * blockDim.x + threadIdx.x;
    if (idx < KB16 * 32 * NB2 * 2) {
        int j    = idx & 1;
        int nb   = (idx >> 1) % NB2;
        int lane = ((idx >> 1) / NB2) & 31;
        int kb   = (idx >> 1) / (NB2 * 32);
        int k0 = kb * 16 + 2 * (lane & 3) + j * 8;
        int n  = nb * 8 + (lane >> 2);
        unsigned short ha, la, hb, lb;
        bf16_split(W2[k0 * HID + n],       ha, la);
        bf16_split(W2[(k0 + 1) * HID + n], hb, lb);
        int o = (kb * 32 + lane) * WSTR2 + nb * 2 + j;
        g_Whi2[o] = pk(ha, hb);
        g_Wlo2[o] = pk(la, lb);
    }
    if (idx < KB16 * 32 * NB3 * 2) {
        int j    = idx & 1;
        int nb   = (idx >> 1) % NB3;
        int lane = ((idx >> 1) / NB3) & 31;
        int kb   = (idx >> 1) / (NB3 * 32);
        int k0 = kb * 16 + 2 * (lane & 3) + j * 8;
        int n  = nb * 8 + (lane >> 2);
        unsigned short ha, la, hb, lb;
        bf16_split(W3[k0 * OUTD + n],       ha, la);
        bf16_split(W3[(k0 + 1) * OUTD + n], hb, lb);
        int o = (kb * 32 + lane) * WSTR3 + nb * 2 + j;
        g_Whi3[o] = pk(ha, hb);
        g_Wlo3[o] = pk(la, lb);
    }
}

// C[MT, NBn*8] = act(A[MT,128] @ W + b): bf16 split GEMM (hh + hl + lh).
template <int NBn, int WSTR, bool RELU>
__device__ __forceinline__ void layer(float* __restrict__ Asf, unsigned* Wp,
                                      const unsigned* __restrict__ g_hi,
                                      const unsigned* __restrict__ g_lo,
                                      const float* bias,
                                      int rows0, int lane, int tid)
{
    const int NW  = KB16 * 32 * WSTR;
    const int NW4 = NW / 4;
    unsigned* Wlo = Wp + NW;
    for (int i = tid; i < NW4; i += NTHREADS) {
        ((uint4*)Wp)[i]  = ((const uint4*)g_hi)[i];
        ((uint4*)Wlo)[i] = ((const uint4*)g_lo)[i];
    }
    __syncthreads();

    float acc[NBn][4];
    int cg = (lane & 3) * 2;
#pragma unroll
    for (int nb = 0; nb < NBn; nb++) {
        float v0 = bias[nb * 8 + cg], v1 = bias[nb * 8 + cg + 1];
        acc[nb][0] = v0; acc[nb][1] = v1; acc[nb][2] = v0; acc[nb][3] = v1;
    }
    int ar = rows0 + (lane >> 2);

#pragma unroll
    for (int kb = 0; kb < KB16; kb++) {
        int c0 = kb * 16 + 2 * (lane & 3);
        float2 p0 = *reinterpret_cast<const float2*>(&Asf[ar * LDA + c0]);
        float2 p1 = *reinterpret_cast<const float2*>(&Asf[(ar + 8) * LDA + c0]);
        float2 p2 = *reinterpret_cast<const float2*>(&Asf[ar * LDA + c0 + 8]);
        float2 p3 = *reinterpret_cast<const float2*>(&Asf[(ar + 8) * LDA + c0 + 8]);
        unsigned short h0a, l0a, h0b, l0b, h1a, l1a, h1b, l1b;
        unsigned short h2a, l2a, h2b, l2b, h3a, l3a, h3b, l3b;
        bf16_split(p0.x, h0a, l0a); bf16_split(p0.y, h0b, l0b);
        bf16_split(p1.x, h1a, l1a); bf16_split(p1.y, h1b, l1b);
        bf16_split(p2.x, h2a, l2a); bf16_split(p2.y, h2b, l2b);
        bf16_split(p3.x, h3a, l3a); bf16_split(p3.y, h3b, l3b);
        unsigned ah0 = pk(h0a, h0b), ah1 = pk(h1a, h1b);
        unsigned ah2 = pk(h2a, h2b), ah3 = pk(h3a, h3b);
        unsigned al0 = pk(l0a, l0b), al1 = pk(l1a, l1b);
        unsigned al2 = pk(l2a, l2b), al3 = pk(l3a, l3b);

        const unsigned* whr = Wp  + (kb * 32 + lane) * WSTR;
        const unsigned* wlr = Wlo + (kb * 32 + lane) * WSTR;
#pragma unroll
        for (int np = 0; np < NBn / 2; np++) {
            uint4 bh = *reinterpret_cast<const uint4*>(whr + np * 4);
            uint4 bl = *reinterpret_cast<const uint4*>(wlr + np * 4);
            MMA_BF16(acc[2 * np],     ah0, ah1, ah2, ah3, bh.x, bh.y);
            MMA_BF16(acc[2 * np],     ah0, ah1, ah2, ah3, bl.x, bl.y);
            MMA_BF16(acc[2 * np],     al0, al1, al2, al3, bh.x, bh.y);
            MMA_BF16(acc[2 * np + 1], ah0, ah1, ah2, ah3, bh.z, bh.w);
            MMA_BF16(acc[2 * np + 1], ah0, ah1, ah2, ah3, bl.z, bl.w);
            MMA_BF16(acc[2 * np + 1], al0, al1, al2, al3, bh.z, bh.w);
        }
    }
    __syncthreads();

    int r0 = rows0 + (lane >> 2);
#pragma unroll
    for (int nb = 0; nb < NBn; nb++) {
        int col = nb * 8 + cg;
        float v0 = acc[nb][0], v1 = acc[nb][1], v2 = acc[nb][2], v3 = acc[nb][3];
        if (RELU) {
            v0 = fmaxf(v0, 0.f); v1 = fmaxf(v1, 0.f);
            v2 = fmaxf(v2, 0.f); v3 = fmaxf(v3, 0.f);
        }
        Asf[r0 * LDA + col]           = v0;
        Asf[r0 * LDA + col + 1]       = v1;
        Asf[(r0 + 8) * LDA + col]     = v2;
        Asf[(r0 + 8) * LDA + col + 1] = v3;
    }
    __syncthreads();
}

__global__ void __launch_bounds__(NTHREADS, 1) gnn_kernel(
    const float* __restrict__ pos, const int* __restrict__ z,
    const int* __restrict__ batch, const float* __restrict__ W1,
    const float* __restrict__ b2, const float* __restrict__ b3, int N)
{
    extern __shared__ float smem[];
    float*    Asf = smem;                                // MT*LDA
    unsigned* Wp  = (unsigned*)(Asf + MT * LDA);         // 2*KB16*32*WSTR2
    float*    bs2 = (float*)(Wp + 2 * KB16 * 32 * WSTR2);
    float*    bs3 = bs2 + HID;
    float*    w1p = bs3 + OUTD;                          // 384
    float*    spos = w1p + 384;                          // 3*MT
    int*      sb  = (int*)(spos + 3 * MT);               // MT
    int*      sz  = sb + MT;                             // MT

    int tid = threadIdx.x, lane = tid & 31, wid = tid >> 5;
    int node0 = blockIdx.x * MT;

    if (tid < MT) {
        int node = node0 + tid;
        sb[tid] = (node < N) ? batch[node] : -1;
        sz[tid] = (node < N) ? z[node] : 0;
    }
    for (int idx = tid; idx < 3 * MT; idx += NTHREADS) {
        int g = node0 * 3 + idx;
        spos[idx] = (g < N * 3) ? pos[g] : 0.f;
    }
    // FIX (root cause of R2-R6 failures): 384 > NTHREADS, must stride
    for (int idx = tid; idx < 384; idx += NTHREADS) w1p[idx] = W1[idx];
    if (tid < HID)  bs2[tid] = b2[tid];
    if (tid < OUTD) bs3[tid] = b3[tid];
    __syncthreads();

    // layer 1 (exact fp32): h1 = relu(E1[z] + pos @ W1[0:3])
    for (int idx = tid; idx < MT * HID; idx += NTHREADS) {
        int i = idx >> 7, c = idx & 127;
        float v = g_E1[sz[i] * HID + c];
        v = fmaf(spos[i * 3 + 0], w1p[c], v);
        v = fmaf(spos[i * 3 + 1], w1p[128 + c], v);
        v = fmaf(spos[i * 3 + 2], w1p[256 + c], v);
        Asf[i * LDA + c] = fmaxf(v, 0.f);
    }
    __syncthreads();

    layer<NB2, WSTR2, true >(Asf, Wp, g_Whi2, g_Wlo2, bs2, wid * 16, lane, tid);
    layer<NB3, WSTR3, false>(Asf, Wp, g_Whi3, g_Wlo3, bs3, wid * 16, lane, tid);

    // segment reduction (batch sorted): 4 row-chunks x 64 cols
    {
        int col = tid & 63, chunk = tid >> 6;
        int i0 = chunk * 32, i1 = i0 + 32;
        float sum = 0.f; int cur = -1;
        for (int i = i0; i < i1; i++) {
            int b = sb[i];
            if (b != cur) {
                if (cur >= 0) atomicAdd(&g_accum[cur * OUTD + col], sum);
                sum = 0.f; cur = b;
            }
            if (b >= 0) sum += Asf[i * LDA + col];
        }
        if (cur >= 0) atomicAdd(&g_accum[cur * OUTD + col], sum);
    }
    if (tid < 4) {
        int i0 = tid * 32, i1 = i0 + 32;
        float c = 0.f; int cur = -1;
        for (int i = i0; i < i1; i++) {
            int b = sb[i];
            if (b != cur) {
                if (cur >= 0) atomicAdd(&g_cnt[cur], c);
                c = 0.f; cur = b;
            }
            if (b >= 0) c += 1.f;
        }
        if (cur >= 0) atomicAdd(&g_cnt[cur], c);
    }
}

__global__ void finalize_kernel(float* __restrict__ out) {
    int idx = blockIdx.x * blockDim.x + threadIdx.x;
    if (idx < NG * OUTD)
        out[idx] = g_accum[idx] / fmaxf(g_cnt[idx >> 6], 1.0f);
}

extern "C" void kernel_launch(void* const* d_in, const int* in_sizes, int n_in,
                              void* d_out, int out_size)
{
    const float* pos   = (const float*)d_in[0];
    const int*   z     = (const int*)  d_in[1];
    const int*   batch = (const int*)  d_in[2];
    const float* emb   = (const float*)d_in[3];
    const float* W1    = (const float*)d_in[4];
    const float* b1    = (const float*)d_in[5];
    const float* W2    = (const float*)d_in[6];
    const float* b2    = (const float*)d_in[7];
    const float* W3    = (const float*)d_in[8];
    const float* b3    = (const float*)d_in[9];

    int N = in_sizes[1];

    size_t smem_bytes = (size_t)(MT * LDA + 2 * KB16 * 32 * WSTR2) * 4
                      + (size_t)(HID + OUTD + 384 + 3 * MT) * 4
                      + (size_t)(2 * MT) * 4;
    cudaFuncSetAttribute(gnn_kernel, cudaFuncAttributeMaxDynamicSharedMemorySize,
                         (int)smem_bytes);

    e1_kernel<<<NTYPES, HID>>>(emb, W1, b1);
    permute_w_kernel<<<(KB16 * 32 * NB2 * 2 + 255) / 256, 256>>>(W2, W3);
    zero_kernel<<<(NG * OUTD + 255) / 256, 256>>>();

    int blocks = (N + MT - 1) / MT;
    gnn_kernel<<<blocks, NTHREADS, smem_bytes>>>(pos, z, batch, W1, b2, b3, N);

    finalize_kernel<<<(NG * OUTD + 255) / 256, 256>>>((float*)d_out);
}

// round 9
// speedup vs baseline: 6.1051x; 1.4343x over previous
#include <cuda_runtime.h>
#include <cuda_bf16.h>

#define NG      4096
#define OUTD    64
#define HID     128
#define NFEAT   125
#define NTYPES  100
#define MT      128
#define NTHREADS 256
#define KB16    8
#define NB2     16
#define NB3     8
#define WSTR2   36
#define WSTR3   20
#define NW2     (KB16 * 32 * WSTR2)   // 9216 words per W2 part
#define NW3     (KB16 * 32 * WSTR3)   // 5120 words per W3 part
#define YSTR    72                     // y smem row stride (conflict-free STS.64)

__device__ float    g_accum[NG * OUTD];
__device__ float    g_cnt[NG];
__device__ float    g_E1[NTYPES * HID];
__device__ unsigned g_Whi2[NW2];
__device__ unsigned g_Wlo2[NW2];
__device__ unsigned g_Whi3[NW3];
__device__ unsigned g_Wlo3[NW3];

__device__ __forceinline__ void bf16_split(float f, unsigned short& h, unsigned short& l) {
    __nv_bfloat16 hb = __float2bfloat16(f);
    __nv_bfloat16 lb = __float2bfloat16(f - __bfloat162float(hb));
    h = __bfloat16_as_ushort(hb);
    l = __bfloat16_as_ushort(lb);
}
__device__ __forceinline__ unsigned pk(unsigned short e0, unsigned short e1) {
    return (unsigned)e0 | ((unsigned)e1 << 16);
}
// split two fp32 into packed bf16 hi / lo fragment words
__device__ __forceinline__ void split_pack(float f0, float f1, unsigned& h, unsigned& l) {
    unsigned short h0, l0, h1, l1;
    bf16_split(f0, h0, l0);
    bf16_split(f1, h1, l1);
    h = pk(h0, h1);
    l = pk(l0, l1);
}

#define MMA_BF16(c, a0, a1, a2, a3, b0, b1)                                   \
    asm volatile("mma.sync.aligned.m16n8k16.row.col.f32.bf16.bf16.f32 "       \
                 "{%0,%1,%2,%3},{%4,%5,%6,%7},{%8,%9},{%0,%1,%2,%3};"         \
                 : "+f"(c[0]), "+f"(c[1]), "+f"(c[2]), "+f"(c[3])             \
                 : "r"(a0), "r"(a1), "r"(a2), "r"(a3), "r"(b0), "r"(b1))

__global__ void e1_kernel(const float* __restrict__ emb,
                          const float* __restrict__ W1,
                          const float* __restrict__ b1) {
    __shared__ float e[NFEAT];
    int t = blockIdx.x, c = threadIdx.x;
    if (c < NFEAT) e[c] = emb[t * NFEAT + c];
    __syncthreads();
    float s = b1[c];
#pragma unroll 5
    for (int d = 0; d < NFEAT; d++)
        s = fmaf(e[d], W1[(3 + d) * HID + c], s);
    g_E1[t * HID + c] = s;
}

__global__ void zero_kernel() {
    int idx = blockIdx.x * blockDim.x + threadIdx.x;
    if (idx < NG * OUTD) g_accum[idx] = 0.0f;
    if (idx < NG)        g_cnt[idx]   = 0.0f;
}

__global__ void permute_w_kernel(const float* __restrict__ W2,
                                 const float* __restrict__ W3) {
    int idx = blockIdx.x * blockDim.x + threadIdx.x;
    if (idx < KB16 * 32 * NB2 * 2) {
        int j    = idx & 1;
        int nb   = (idx >> 1) % NB2;
        int lane = ((idx >> 1) / NB2) & 31;
        int kb   = (idx >> 1) / (NB2 * 32);
        int k0 = kb * 16 + 2 * (lane & 3) + j * 8;
        int n  = nb * 8 + (lane >> 2);
        unsigned short ha, la, hb, lb;
        bf16_split(W2[k0 * HID + n],       ha, la);
        bf16_split(W2[(k0 + 1) * HID + n], hb, lb);
        int o = (kb * 32 + lane) * WSTR2 + nb * 2 + j;
        g_Whi2[o] = pk(ha, hb);
        g_Wlo2[o] = pk(la, lb);
    }
    if (idx < KB16 * 32 * NB3 * 2) {
        int j    = idx & 1;
        int nb   = (idx >> 1) % NB3;
        int lane = ((idx >> 1) / NB3) & 31;
        int kb   = (idx >> 1) / (NB3 * 32);
        int k0 = kb * 16 + 2 * (lane & 3) + j * 8;
        int n  = nb * 8 + (lane >> 2);
        unsigned short ha, la, hb, lb;
        bf16_split(W3[k0 * OUTD + n],       ha, la);
        bf16_split(W3[(k0 + 1) * OUTD + n], hb, lb);
        int o = (kb * 32 + lane) * WSTR3 + nb * 2 + j;
        g_Whi3[o] = pk(ha, hb);
        g_Wlo3[o] = pk(la, lb);
    }
}

__global__ void __launch_bounds__(NTHREADS) gnn_kernel(
    const float* __restrict__ pos, const int* __restrict__ z,
    const int* __restrict__ batch, const float* __restrict__ W1,
    const float* __restrict__ b2, const float* __restrict__ b3, int N)
{
    extern __shared__ unsigned smem[];
    unsigned* Wp2  = smem;                    // 2*NW2 (hi | lo)
    unsigned* Wp3  = Wp2 + 2 * NW2;           // 2*NW3 (hi | lo); reused as yb
    float*    bs2  = (float*)(Wp3 + 2 * NW3); // 128
    float*    bs3  = bs2 + HID;               // 64
    float*    w1p  = bs3 + OUTD;              // 384
    float*    spos = w1p + 384;               // 3*MT
    int*      sb   = (int*)(spos + 3 * MT);   // MT
    int*      sz   = sb + MT;                 // MT
    float*    yb   = (float*)Wp3;             // MT*YSTR = 9216 <= 2*NW3

    int tid = threadIdx.x, lane = tid & 31, wid = tid >> 5;
    int cg = (lane & 3) * 2;
    int node0 = blockIdx.x * MT;

    if (tid < MT) {
        int node = node0 + tid;
        sb[tid] = (node < N) ? batch[node] : -1;
        sz[tid] = (node < N) ? z[node] : 0;
    }
    for (int idx = tid; idx < 3 * MT; idx += NTHREADS) {
        int g = node0 * 3 + idx;
        spos[idx] = (g < N * 3) ? pos[g] : 0.f;
    }
    for (int idx = tid; idx < 384; idx += NTHREADS) w1p[idx] = W1[idx];
    if (tid < HID)  bs2[tid] = b2[tid];
    if (tid < OUTD) bs3[tid] = b3[tid];
    // stage all weights once (uint4)
    for (int i = tid; i < NW2 / 4; i += NTHREADS) {
        ((uint4*)Wp2)[i]             = ((const uint4*)g_Whi2)[i];
        ((uint4*)(Wp2 + NW2))[i]     = ((const uint4*)g_Wlo2)[i];
    }
    for (int i = tid; i < NW3 / 4; i += NTHREADS) {
        ((uint4*)Wp3)[i]             = ((const uint4*)g_Whi3)[i];
        ((uint4*)(Wp3 + NW3))[i]     = ((const uint4*)g_Wlo3)[i];
    }
    __syncthreads();

    // ---- layer 1 directly into C-fragment layout (fp32 registers) ----
    // v[nb][0..3]: rows (r, r, r+8, r+8), cols (8nb+cg, +1, 8nb+cg, +1)
    int r_lo = wid * 16 + (lane >> 2);
    int r_hi = r_lo + 8;
    const float* e1l = g_E1 + sz[r_lo] * HID;
    const float* e1h = g_E1 + sz[r_hi] * HID;
    float pl0 = spos[3 * r_lo], pl1 = spos[3 * r_lo + 1], pl2 = spos[3 * r_lo + 2];
    float ph0 = spos[3 * r_hi], ph1 = spos[3 * r_hi + 1], ph2 = spos[3 * r_hi + 2];

    float v[NB2][4];
#pragma unroll
    for (int nb = 0; nb < NB2; nb++) {
        int c = nb * 8 + cg;
        float2 el = *reinterpret_cast<const float2*>(e1l + c);
        float2 eh = *reinterpret_cast<const float2*>(e1h + c);
        float2 wa = *reinterpret_cast<const float2*>(w1p + c);
        float2 wb = *reinterpret_cast<const float2*>(w1p + 128 + c);
        float2 wc = *reinterpret_cast<const float2*>(w1p + 256 + c);
        v[nb][0] = fmaxf(fmaf(pl2, wc.x, fmaf(pl1, wb.x, fmaf(pl0, wa.x, el.x))), 0.f);
        v[nb][1] = fmaxf(fmaf(pl2, wc.y, fmaf(pl1, wb.y, fmaf(pl0, wa.y, el.y))), 0.f);
        v[nb][2] = fmaxf(fmaf(ph2, wc.x, fmaf(ph1, wb.x, fmaf(ph0, wa.x, eh.x))), 0.f);
        v[nb][3] = fmaxf(fmaf(ph2, wc.y, fmaf(ph1, wb.y, fmaf(ph0, wa.y, eh.y))), 0.f);
    }

    // ---- layer 2: acc = relu(v @ W2 + b2), fragments stay in registers ----
    float acc[NB2][4];
#pragma unroll
    for (int nb = 0; nb < NB2; nb++) {
        float b0 = bs2[nb * 8 + cg], b1v = bs2[nb * 8 + cg + 1];
        acc[nb][0] = b0; acc[nb][1] = b1v; acc[nb][2] = b0; acc[nb][3] = b1v;
    }
#pragma unroll
    for (int kb = 0; kb < KB16; kb++) {
        unsigned ah0, al0, ah1, al1, ah2, al2, ah3, al3;
        split_pack(v[2 * kb][0],     v[2 * kb][1],     ah0, al0);
        split_pack(v[2 * kb][2],     v[2 * kb][3],     ah1, al1);
        split_pack(v[2 * kb + 1][0], v[2 * kb + 1][1], ah2, al2);
        split_pack(v[2 * kb + 1][2], v[2 * kb + 1][3], ah3, al3);
        const unsigned* whr = Wp2 + (kb * 32 + lane) * WSTR2;
        const unsigned* wlr = whr + NW2;
#pragma unroll
        for (int np = 0; np < NB2 / 2; np++) {
            uint4 bh = *reinterpret_cast<const uint4*>(whr + np * 4);
            uint4 bl = *reinterpret_cast<const uint4*>(wlr + np * 4);
            MMA_BF16(acc[2 * np],     ah0, ah1, ah2, ah3, bh.x, bh.y);
            MMA_BF16(acc[2 * np],     ah0, ah1, ah2, ah3, bl.x, bl.y);
            MMA_BF16(acc[2 * np],     al0, al1, al2, al3, bh.x, bh.y);
            MMA_BF16(acc[2 * np + 1], ah0, ah1, ah2, ah3, bh.z, bh.w);
            MMA_BF16(acc[2 * np + 1], ah0, ah1, ah2, ah3, bl.z, bl.w);
            MMA_BF16(acc[2 * np + 1], al0, al1, al2, al3, bh.z, bh.w);
        }
    }
#pragma unroll
    for (int nb = 0; nb < NB2; nb++)
#pragma unroll
        for (int j = 0; j < 4; j++)
            v[nb][j] = fmaxf(acc[nb][j], 0.f);

    // ---- layer 3: y = v @ W3 + b3 ----
    float acc3[NB3][4];
#pragma unroll
    for (int nb = 0; nb < NB3; nb++) {
        float b0 = bs3[nb * 8 + cg], b1v = bs3[nb * 8 + cg + 1];
        acc3[nb][0] = b0; acc3[nb][1] = b1v; acc3[nb][2] = b0; acc3[nb][3] = b1v;
    }
#pragma unroll
    for (int kb = 0; kb < KB16; kb++) {
        unsigned ah0, al0, ah1, al1, ah2, al2, ah3, al3;
        split_pack(v[2 * kb][0],     v[2 * kb][1],     ah0, al0);
        split_pack(v[2 * kb][2],     v[2 * kb][3],     ah1, al1);
        split_pack(v[2 * kb + 1][0], v[2 * kb + 1][1], ah2, al2);
        split_pack(v[2 * kb + 1][2], v[2 * kb + 1][3], ah3, al3);
        const unsigned* whr = Wp3 + (kb * 32 + lane) * WSTR3;
        const unsigned* wlr = whr + NW3;
#pragma unroll
        for (int np = 0; np < NB3 / 2; np++) {
            uint4 bh = *reinterpret_cast<const uint4*>(whr + np * 4);
            uint4 bl = *reinterpret_cast<const uint4*>(wlr + np * 4);
            MMA_BF16(acc3[2 * np],     ah0, ah1, ah2, ah3, bh.x, bh.y);
            MMA_BF16(acc3[2 * np],     ah0, ah1, ah2, ah3, bl.x, bl.y);
            MMA_BF16(acc3[2 * np],     al0, al1, al2, al3, bh.x, bh.y);
            MMA_BF16(acc3[2 * np + 1], ah0, ah1, ah2, ah3, bh.z, bh.w);
            MMA_BF16(acc3[2 * np + 1], ah0, ah1, ah2, ah3, bl.z, bl.w);
            MMA_BF16(acc3[2 * np + 1], al0, al1, al2, al3, bh.z, bh.w);
        }
    }

    // all warps done reading Wp3 -> safe to overwrite with y
    __syncthreads();
#pragma unroll
    for (int nb = 0; nb < NB3; nb++) {
        int col = nb * 8 + cg;
        *reinterpret_cast<float2*>(&yb[r_lo * YSTR + col]) =
            make_float2(acc3[nb][0], acc3[nb][1]);
        *reinterpret_cast<float2*>(&yb[r_hi * YSTR + col]) =
            make_float2(acc3[nb][2], acc3[nb][3]);
    }
    __syncthreads();

    // segment reduction (batch sorted): 4 row-chunks x 64 cols
    {
        int col = tid & 63, chunk = tid >> 6;
        int i0 = chunk * 32, i1 = i0 + 32;
        float sum = 0.f; int cur = -1;
        for (int i = i0; i < i1; i++) {
            int b = sb[i];
            if (b != cur) {
                if (cur >= 0) atomicAdd(&g_accum[cur * OUTD + col], sum);
                sum = 0.f; cur = b;
            }
            if (b >= 0) sum += yb[i * YSTR + col];
        }
        if (cur >= 0) atomicAdd(&g_accum[cur * OUTD + col], sum);
    }
    if (tid < 4) {
        int i0 = tid * 32, i1 = i0 + 32;
        float c = 0.f; int cur = -1;
        for (int i = i0; i < i1; i++) {
            int b = sb[i];
            if (b != cur) {
                if (cur >= 0) atomicAdd(&g_cnt[cur], c);
                c = 0.f; cur = b;
            }
            if (b >= 0) c += 1.f;
        }
        if (cur >= 0) atomicAdd(&g_cnt[cur], c);
    }
}

__global__ void finalize_kernel(float* __restrict__ out) {
    int idx = blockIdx.x * blockDim.x + threadIdx.x;
    if (idx < NG * OUTD)
        out[idx] = g_accum[idx] / fmaxf(g_cnt[idx >> 6], 1.0f);
}

extern "C" void kernel_launch(void* const* d_in, const int* in_sizes, int n_in,
                              void* d_out, int out_size)
{
    const float* pos   = (const float*)d_in[0];
    const int*   z     = (const int*)  d_in[1];
    const int*   batch = (const int*)  d_in[2];
    const float* emb   = (const float*)d_in[3];
    const float* W1    = (const float*)d_in[4];
    const float* b1    = (const float*)d_in[5];
    const float* W2    = (const float*)d_in[6];
    const float* b2    = (const float*)d_in[7];
    const float* W3    = (const float*)d_in[8];
    const float* b3    = (const float*)d_in[9];

    int N = in_sizes[1];

    size_t smem_bytes = (size_t)(2 * NW2 + 2 * NW3) * 4
                      + (size_t)(HID + OUTD + 384 + 3 * MT) * 4
                      + (size_t)(2 * MT) * 4;
    cudaFuncSetAttribute(gnn_kernel, cudaFuncAttributeMaxDynamicSharedMemorySize,
                         (int)smem_bytes);

    e1_kernel<<<NTYPES, HID>>>(emb, W1, b1);
    permute_w_kernel<<<(KB16 * 32 * NB2 * 2 + 255) / 256, 256>>>(W2, W3);
    zero_kernel<<<(NG * OUTD + 255) / 256, 256>>>();

    int blocks = (N + MT - 1) / MT;
    gnn_kernel<<<blocks, NTHREADS, smem_bytes>>>(pos, z, batch, W1, b2, b3, N);

    finalize_kernel<<<(NG * OUTD + 255) / 256, 256>>>((float*)d_out);
}

// round 10
// speedup vs baseline: 6.2138x; 1.0178x over previous
#include <cuda_runtime.h>
#include <cuda_bf16.h>

#define NG      4096
#define OUTD    64
#define HID     128
#define NFEAT   125
#define NTYPES  100
#define MT      128
#define NTHREADS 512
#define KB16    8
#define NB2     16
#define NB3     8
#define WSTR2   36
#define WSTR3   20
#define NW2     (KB16 * 32 * WSTR2)   // 9216 words per W2 part
#define NW3     (KB16 * 32 * WSTR3)   // 5120 words per W3 part
#define XSTR    68                     // exchange/y row stride (conflict-free)

__device__ float    g_accum[NG * OUTD];
__device__ float    g_cnt[NG];
__device__ float    g_E1[NTYPES * HID];
__device__ unsigned g_Whi2[NW2];
__device__ unsigned g_Wlo2[NW2];
__device__ unsigned g_Whi3[NW3];
__device__ unsigned g_Wlo3[NW3];

__device__ __forceinline__ void bf16_split(float f, unsigned short& h, unsigned short& l) {
    __nv_bfloat16 hb = __float2bfloat16(f);
    __nv_bfloat16 lb = __float2bfloat16(f - __bfloat162float(hb));
    h = __bfloat16_as_ushort(hb);
    l = __bfloat16_as_ushort(lb);
}
__device__ __forceinline__ unsigned pk(unsigned short e0, unsigned short e1) {
    return (unsigned)e0 | ((unsigned)e1 << 16);
}
__device__ __forceinline__ void split_pack(float f0, float f1, unsigned& h, unsigned& l) {
    unsigned short h0, l0, h1, l1;
    bf16_split(f0, h0, l0);
    bf16_split(f1, h1, l1);
    h = pk(h0, h1);
    l = pk(l0, l1);
}

#define MMA_BF16(c, a0, a1, a2, a3, b0, b1)                                   \
    asm volatile("mma.sync.aligned.m16n8k16.row.col.f32.bf16.bf16.f32 "       \
                 "{%0,%1,%2,%3},{%4,%5,%6,%7},{%8,%9},{%0,%1,%2,%3};"         \
                 : "+f"(c[0]), "+f"(c[1]), "+f"(c[2]), "+f"(c[3])             \
                 : "r"(a0), "r"(a1), "r"(a2), "r"(a3), "r"(b0), "r"(b1))

__global__ void e1_kernel(const float* __restrict__ emb,
                          const float* __restrict__ W1,
                          const float* __restrict__ b1) {
    __shared__ float e[NFEAT];
    int t = blockIdx.x, c = threadIdx.x;
    if (c < NFEAT) e[c] = emb[t * NFEAT + c];
    __syncthreads();
    float s = b1[c];
#pragma unroll 5
    for (int d = 0; d < NFEAT; d++)
        s = fmaf(e[d], W1[(3 + d) * HID + c], s);
    g_E1[t * HID + c] = s;
}

__global__ void zero_kernel() {
    int idx = blockIdx.x * blockDim.x + threadIdx.x;
    if (idx < NG * OUTD) g_accum[idx] = 0.0f;
    if (idx < NG)        g_cnt[idx]   = 0.0f;
}

__global__ void permute_w_kernel(const float* __restrict__ W2,
                                 const float* __restrict__ W3) {
    int idx = blockIdx.x * blockDim.x + threadIdx.x;
    if (idx < KB16 * 32 * NB2 * 2) {
        int j    = idx & 1;
        int nb   = (idx >> 1) % NB2;
        int lane = ((idx >> 1) / NB2) & 31;
        int kb   = (idx >> 1) / (NB2 * 32);
        int k0 = kb * 16 + 2 * (lane & 3) + j * 8;
        int n  = nb * 8 + (lane >> 2);
        unsigned short ha, la, hb, lb;
        bf16_split(W2[k0 * HID + n],       ha, la);
        bf16_split(W2[(k0 + 1) * HID + n], hb, lb);
        int o = (kb * 32 + lane) * WSTR2 + nb * 2 + j;
        g_Whi2[o] = pk(ha, hb);
        g_Wlo2[o] = pk(la, lb);
    }
    if (idx < KB16 * 32 * NB3 * 2) {
        int j    = idx & 1;
        int nb   = (idx >> 1) % NB3;
        int lane = ((idx >> 1) / NB3) & 31;
        int kb   = (idx >> 1) / (NB3 * 32);
        int k0 = kb * 16 + 2 * (lane & 3) + j * 8;
        int n  = nb * 8 + (lane >> 2);
        unsigned short ha, la, hb, lb;
        bf16_split(W3[k0 * OUTD + n],       ha, la);
        bf16_split(W3[(k0 + 1) * OUTD + n], hb, lb);
        int o = (kb * 32 + lane) * WSTR3 + nb * 2 + j;
        g_Whi3[o] = pk(ha, hb);
        g_Wlo3[o] = pk(la, lb);
    }
}

__global__ void __launch_bounds__(NTHREADS, 1) gnn_kernel(
    const float* __restrict__ pos, const int* __restrict__ z,
    const int* __restrict__ batch, const float* __restrict__ W1,
    const float* __restrict__ b2, const float* __restrict__ b3, int N)
{
    extern __shared__ unsigned smem[];
    unsigned* Wp2  = smem;                    // 2*NW2 (hi | lo); later overlaid by xb/yb
    unsigned* Wp3  = Wp2 + 2 * NW2;           // 2*NW3 (hi | lo)
    float*    bs2  = (float*)(Wp3 + 2 * NW3); // 128
    float*    bs3  = bs2 + HID;               // 64
    float*    w1p  = bs3 + OUTD;              // 384
    float*    spos = w1p + 384;               // 3*MT
    int*      sb   = (int*)(spos + 3 * MT);   // MT
    int*      sz   = sb + MT;                 // MT
    float*    xb   = (float*)Wp2;             // MT*XSTR overlay (exchange)
    float*    yb   = xb + MT * XSTR;          // MT*XSTR overlay (final y)

    int tid = threadIdx.x, lane = tid & 31, wid = tid >> 5;
    int grp = wid >> 1;           // 16-row group 0..7
    int odd = wid & 1;            // N/K split half
    int cg  = (lane & 3) * 2;
    int node0 = blockIdx.x * MT;

    if (tid < MT) {
        int node = node0 + tid;
        sb[tid] = (node < N) ? batch[node] : -1;
        sz[tid] = (node < N) ? z[node] : 0;
    }
    for (int idx = tid; idx < 3 * MT; idx += NTHREADS) {
        int g = node0 * 3 + idx;
        spos[idx] = (g < N * 3) ? pos[g] : 0.f;
    }
    for (int idx = tid; idx < 384; idx += NTHREADS) w1p[idx] = W1[idx];
    if (tid < HID)  bs2[tid] = b2[tid];
    if (tid < OUTD) bs3[tid] = b3[tid];
    for (int i = tid; i < NW2 / 4; i += NTHREADS) {
        ((uint4*)Wp2)[i]         = ((const uint4*)g_Whi2)[i];
        ((uint4*)(Wp2 + NW2))[i] = ((const uint4*)g_Wlo2)[i];
    }
    for (int i = tid; i < NW3 / 4; i += NTHREADS) {
        ((uint4*)Wp3)[i]         = ((const uint4*)g_Whi3)[i];
        ((uint4*)(Wp3 + NW3))[i] = ((const uint4*)g_Wlo3)[i];
    }
    __syncthreads();

    // ---- layer 1: full 128-col fragment activations (duplicated in pair) ----
    int r_lo = grp * 16 + (lane >> 2);
    int r_hi = r_lo + 8;
    const float* e1l = g_E1 + sz[r_lo] * HID;
    const float* e1h = g_E1 + sz[r_hi] * HID;
    float pl0 = spos[3 * r_lo], pl1 = spos[3 * r_lo + 1], pl2 = spos[3 * r_lo + 2];
    float ph0 = spos[3 * r_hi], ph1 = spos[3 * r_hi + 1], ph2 = spos[3 * r_hi + 2];

    float v[NB2][4];
#pragma unroll
    for (int nb = 0; nb < NB2; nb++) {
        int c = nb * 8 + cg;
        float2 el = *reinterpret_cast<const float2*>(e1l + c);
        float2 eh = *reinterpret_cast<const float2*>(e1h + c);
        float2 wa = *reinterpret_cast<const float2*>(w1p + c);
        float2 wb = *reinterpret_cast<const float2*>(w1p + 128 + c);
        float2 wc = *reinterpret_cast<const float2*>(w1p + 256 + c);
        v[nb][0] = fmaxf(fmaf(pl2, wc.x, fmaf(pl1, wb.x, fmaf(pl0, wa.x, el.x))), 0.f);
        v[nb][1] = fmaxf(fmaf(pl2, wc.y, fmaf(pl1, wb.y, fmaf(pl0, wa.y, el.y))), 0.f);
        v[nb][2] = fmaxf(fmaf(ph2, wc.x, fmaf(ph1, wb.x, fmaf(ph0, wa.x, eh.x))), 0.f);
        v[nb][3] = fmaxf(fmaf(ph2, wc.y, fmaf(ph1, wb.y, fmaf(ph0, wa.y, eh.y))), 0.f);
    }

    // ---- layer 2 (N-split): this warp computes 8 n-blocks (cols odd*64 ..) ----
    float acc[8][4];
#pragma unroll
    for (int nb = 0; nb < 8; nb++) {
        int c = (odd * 8 + nb) * 8 + cg;
        acc[nb][0] = bs2[c]; acc[nb][1] = bs2[c + 1];
        acc[nb][2] = bs2[c]; acc[nb][3] = bs2[c + 1];
    }
#pragma unroll
    for (int kb = 0; kb < KB16; kb++) {
        unsigned ah0, al0, ah1, al1, ah2, al2, ah3, al3;
        split_pack(v[2 * kb][0],     v[2 * kb][1],     ah0, al0);
        split_pack(v[2 * kb][2],     v[2 * kb][3],     ah1, al1);
        split_pack(v[2 * kb + 1][0], v[2 * kb + 1][1], ah2, al2);
        split_pack(v[2 * kb + 1][2], v[2 * kb + 1][3], ah3, al3);
        const unsigned* whr = Wp2 + (kb * 32 + lane) * WSTR2 + odd * 16;
        const unsigned* wlr = whr + NW2;
#pragma unroll
        for (int np = 0; np < 4; np++) {
            uint4 bh = *reinterpret_cast<const uint4*>(whr + np * 4);
            uint4 bl = *reinterpret_cast<const uint4*>(wlr + np * 4);
            MMA_BF16(acc[2 * np],     ah0, ah1, ah2, ah3, bh.x, bh.y);
            MMA_BF16(acc[2 * np],     ah0, ah1, ah2, ah3, bl.x, bl.y);
            MMA_BF16(acc[2 * np],     al0, al1, al2, al3, bh.x, bh.y);
            MMA_BF16(acc[2 * np + 1], ah0, ah1, ah2, ah3, bh.z, bh.w);
            MMA_BF16(acc[2 * np + 1], ah0, ah1, ah2, ah3, bl.z, bl.w);
            MMA_BF16(acc[2 * np + 1], al0, al1, al2, al3, bh.z, bh.w);
        }
    }
    // relu -> v2 half (cols odd*64 .. odd*64+63 = layer3 k-range odd*64..)
    float v2[8][4];
#pragma unroll
    for (int nb = 0; nb < 8; nb++)
#pragma unroll
        for (int j = 0; j < 4; j++)
            v2[nb][j] = fmaxf(acc[nb][j], 0.f);

    // ---- layer 3 (K-split): kb_global = odd*4 + kbl; bias only on even warp ----
    float acc3[NB3][4];
#pragma unroll
    for (int nb = 0; nb < NB3; nb++) {
        float b0 = odd ? 0.f : bs3[nb * 8 + cg];
        float b1v = odd ? 0.f : bs3[nb * 8 + cg + 1];
        acc3[nb][0] = b0; acc3[nb][1] = b1v; acc3[nb][2] = b0; acc3[nb][3] = b1v;
    }
#pragma unroll
    for (int kbl = 0; kbl < 4; kbl++) {
        int kbg = odd * 4 + kbl;
        unsigned ah0, al0, ah1, al1, ah2, al2, ah3, al3;
        split_pack(v2[2 * kbl][0],     v2[2 * kbl][1],     ah0, al0);
        split_pack(v2[2 * kbl][2],     v2[2 * kbl][3],     ah1, al1);
        split_pack(v2[2 * kbl + 1][0], v2[2 * kbl + 1][1], ah2, al2);
        split_pack(v2[2 * kbl + 1][2], v2[2 * kbl + 1][3], ah3, al3);
        const unsigned* whr = Wp3 + (kbg * 32 + lane) * WSTR3;
        const unsigned* wlr = whr + NW3;
#pragma unroll
        for (int np = 0; np < NB3 / 2; np++) {
            uint4 bh = *reinterpret_cast<const uint4*>(whr + np * 4);
            uint4 bl = *reinterpret_cast<const uint4*>(wlr + np * 4);
            MMA_BF16(acc3[2 * np],     ah0, ah1, ah2, ah3, bh.x, bh.y);
            MMA_BF16(acc3[2 * np],     ah0, ah1, ah2, ah3, bl.x, bl.y);
            MMA_BF16(acc3[2 * np],     al0, al1, al2, al3, bh.x, bh.y);
            MMA_BF16(acc3[2 * np + 1], ah0, ah1, ah2, ah3, bh.z, bh.w);
            MMA_BF16(acc3[2 * np + 1], ah0, ah1, ah2, ah3, bl.z, bl.w);
            MMA_BF16(acc3[2 * np + 1], al0, al1, al2, al3, bh.z, bh.w);
        }
    }

    // all warps done with Wp2 -> overlay exchange + y buffers
    __syncthreads();
    if (odd) {
#pragma unroll
        for (int nb = 0; nb < NB3; nb++) {
            int col = nb * 8 + cg;
            *reinterpret_cast<float2*>(&xb[r_lo * XSTR + col]) =
                make_float2(acc3[nb][0], acc3[nb][1]);
            *reinterpret_cast<float2*>(&xb[r_hi * XSTR + col]) =
                make_float2(acc3[nb][2], acc3[nb][3]);
        }
    }
    __syncthreads();
    if (!odd) {
#pragma unroll
        for (int nb = 0; nb < NB3; nb++) {
            int col = nb * 8 + cg;
            float2 xl = *reinterpret_cast<const float2*>(&xb[r_lo * XSTR + col]);
            float2 xh = *reinterpret_cast<const float2*>(&xb[r_hi * XSTR + col]);
            *reinterpret_cast<float2*>(&yb[r_lo * XSTR + col]) =
                make_float2(acc3[nb][0] + xl.x, acc3[nb][1] + xl.y);
            *reinterpret_cast<float2*>(&yb[r_hi * XSTR + col]) =
                make_float2(acc3[nb][2] + xh.x, acc3[nb][3] + xh.y);
        }
    }
    __syncthreads();

    // segment reduction (batch sorted): 8 row-chunks x 64 cols (512 threads)
    {
        int col = tid & 63, chunk = tid >> 6;
        int i0 = chunk * 16, i1 = i0 + 16;
        float sum = 0.f; int cur = -1;
        for (int i = i0; i < i1; i++) {
            int b = sb[i];
            if (b != cur) {
                if (cur >= 0) atomicAdd(&g_accum[cur * OUTD + col], sum);
                sum = 0.f; cur = b;
            }
            if (b >= 0) sum += yb[i * XSTR + col];
        }
        if (cur >= 0) atomicAdd(&g_accum[cur * OUTD + col], sum);
    }
    if (tid < 8) {
        int i0 = tid * 16, i1 = i0 + 16;
        float c = 0.f; int cur = -1;
        for (int i = i0; i < i1; i++) {
            int b = sb[i];
            if (b != cur) {
                if (cur >= 0) atomicAdd(&g_cnt[cur], c);
                c = 0.f; cur = b;
            }
            if (b >= 0) c += 1.f;
        }
        if (cur >= 0) atomicAdd(&g_cnt[cur], c);
    }
}

__global__ void finalize_kernel(float* __restrict__ out) {
    int idx = blockIdx.x * blockDim.x + threadIdx.x;
    if (idx < NG * OUTD)
        out[idx] = g_accum[idx] / fmaxf(g_cnt[idx >> 6], 1.0f);
}

extern "C" void kernel_launch(void* const* d_in, const int* in_sizes, int n_in,
                              void* d_out, int out_size)
{
    const float* pos   = (const float*)d_in[0];
    const int*   z     = (const int*)  d_in[1];
    const int*   batch = (const int*)  d_in[2];
    const float* emb   = (const float*)d_in[3];
    const float* W1    = (const float*)d_in[4];
    const float* b1    = (const float*)d_in[5];
    const float* W2    = (const float*)d_in[6];
    const float* b2    = (const float*)d_in[7];
    const float* W3    = (const float*)d_in[8];
    const float* b3    = (const float*)d_in[9];

    int N = in_sizes[1];

    size_t smem_bytes = (size_t)(2 * NW2 + 2 * NW3) * 4
                      + (size_t)(HID + OUTD + 384 + 3 * MT) * 4
                      + (size_t)(2 * MT) * 4;
    cudaFuncSetAttribute(gnn_kernel, cudaFuncAttributeMaxDynamicSharedMemorySize,
                         (int)smem_bytes);

    e1_kernel<<<NTYPES, HID>>>(emb, W1, b1);
    permute_w_kernel<<<(KB16 * 32 * NB2 * 2 + 255) / 256, 256>>>(W2, W3);
    zero_kernel<<<(NG * OUTD + 255) / 256, 256>>>();

    int blocks = (N + MT - 1) / MT;
    gnn_kernel<<<blocks, NTHREADS, smem_bytes>>>(pos, z, batch, W1, b2, b3, N);

    finalize_kernel<<<(NG * OUTD + 255) / 256, 256>>>((float*)d_out);
}

// round 12
// speedup vs baseline: 6.2351x; 1.0034x over previous
#include <cuda_runtime.h>
#include <cuda_bf16.h>

#define NG      4096
#define OUTD    64
#define HID     128
#define NFEAT   125
#define NTYPES  100
#define MT      128
#define NTHREADS 256
#define GRID_P  152
#define KB16    8
#define NB2     16
#define NB3     8
#define WSTR2   36
#define WSTR3   20
#define NW2     (KB16 * 32 * WSTR2)   // 9216 words per W2 part
#define NW3     (KB16 * 32 * WSTR3)   // 5120 words per W3 part
#define XSTR    66                     // exchange row stride (words)

__device__ float    g_accum[NG * OUTD];
__device__ float    g_cnt[NG];
__device__ float    g_E1[NTYPES * HID];
__device__ unsigned g_Whi2[NW2];
__device__ unsigned g_Wlo2[NW2];
__device__ unsigned g_Whi3[NW3];
__device__ unsigned g_Wlo3[NW3];

__device__ __forceinline__ void bf16_split(float f, unsigned short& h, unsigned short& l) {
    __nv_bfloat16 hb = __float2bfloat16(f);
    __nv_bfloat16 lb = __float2bfloat16(f - __bfloat162float(hb));
    h = __bfloat16_as_ushort(hb);
    l = __bfloat16_as_ushort(lb);
}
__device__ __forceinline__ unsigned pk(unsigned short a, unsigned short b) {
    return (unsigned)a | ((unsigned)b << 16);
}
__device__ __forceinline__ void split_pack(float f0, float f1, unsigned& h, unsigned& l) {
    unsigned short h0, l0, h1, l1;
    bf16_split(f0, h0, l0);
    bf16_split(f1, h1, l1);
    h = pk(h0, h1);
    l = pk(l0, l1);
}

#define MMA_BF16(c, a0, a1, a2, a3, b0, b1)                                   \
    asm volatile("mma.sync.aligned.m16n8k16.row.col.f32.bf16.bf16.f32 "       \
                 "{%0,%1,%2,%3},{%4,%5,%6,%7},{%8,%9},{%0,%1,%2,%3};"         \
                 : "+f"(c[0]), "+f"(c[1]), "+f"(c[2]), "+f"(c[3])             \
                 : "r"(a0), "r"(a1), "r"(a2), "r"(a3), "r"(b0), "r"(b1))

__global__ void e1_kernel(const float* __restrict__ emb,
                          const float* __restrict__ W1,
                          const float* __restrict__ b1) {
    __shared__ float e[NFEAT];
    int t = blockIdx.x, c = threadIdx.x;
    if (c < NFEAT) e[c] = emb[t * NFEAT + c];
    __syncthreads();
    float s = b1[c];
#pragma unroll 5
    for (int d = 0; d < NFEAT; d++)
        s = fmaf(e[d], W1[(3 + d) * HID + c], s);
    g_E1[t * HID + c] = s;
}

__global__ void zero_kernel() {
    int idx = blockIdx.x * blockDim.x + threadIdx.x;
    if (idx < NG * OUTD) g_accum[idx] = 0.0f;
    if (idx < NG)        g_cnt[idx]   = 0.0f;
}

__global__ void permute_w_kernel(const float* __restrict__ W2,
                                 const float* __restrict__ W3) {
    int idx = blockIdx.x * blockDim.x + threadIdx.x;
    if (idx < KB16 * 32 * NB2 * 2) {
        int j    = idx & 1;
        int nb   = (idx >> 1) % NB2;
        int lane = ((idx >> 1) / NB2) & 31;
        int kb   = (idx >> 1) / (NB2 * 32);
        int k0 = kb * 16 + 2 * (lane & 3) + j * 8;
        int n  = nb * 8 + (lane >> 2);
        unsigned short ha, la, hb, lb;
        bf16_split(W2[k0 * HID + n],       ha, la);
        bf16_split(W2[(k0 + 1) * HID + n], hb, lb);
        int o = (kb * 32 + lane) * WSTR2 + nb * 2 + j;
        g_Whi2[o] = pk(ha, hb);
        g_Wlo2[o] = pk(la, lb);
    }
    if (idx < KB16 * 32 * NB3 * 2) {
        int j    = idx & 1;
        int nb   = (idx >> 1) % NB3;
        int lane = ((idx >> 1) / NB3) & 31;
        int kb   = (idx >> 1) / (NB3 * 32);
        int k0 = kb * 16 + 2 * (lane & 3) + j * 8;
        int n  = nb * 8 + (lane >> 2);
        unsigned short ha, la, hb, lb;
        bf16_split(W3[k0 * OUTD + n],       ha, la);
        bf16_split(W3[(k0 + 1) * OUTD + n], hb, lb);
        int o = (kb * 32 + lane) * WSTR3 + nb * 2 + j;
        g_Whi3[o] = pk(ha, hb);
        g_Wlo3[o] = pk(la, lb);
    }
}

__global__ void __launch_bounds__(NTHREADS, 1) gnn_kernel(
    const float* __restrict__ pos, const int* __restrict__ z,
    const int* __restrict__ batch, const float* __restrict__ W1,
    const float* __restrict__ b2, const float* __restrict__ b3,
    int N, int ntiles)
{
    extern __shared__ unsigned smem[];
    unsigned* Wp2  = smem;                    // 2*NW2 (hi | lo)
    unsigned* Wp3  = Wp2 + 2 * NW2;           // 2*NW3 (hi | lo)
    float*    xb   = (float*)(Wp3 + 2 * NW3); // MT*XSTR exchange/y
    float*    bs2  = xb + MT * XSTR;          // 128
    float*    bs3  = bs2 + HID;               // 64
    float*    w1p  = bs3 + OUTD;              // 384
    float*    spos = w1p + 384;               // 3*MT
    int*      sb   = (int*)(spos + 3 * MT);   // MT
    int*      sz   = sb + MT;                 // MT

    int tid = threadIdx.x, lane = tid & 31, wid = tid >> 5;
    int grp = wid >> 1;           // 32-row group 0..3
    int odd = wid & 1;            // N/K split half
    int cg  = (lane & 3) * 2;

    // one-time weight staging
    for (int i = tid; i < NW2 / 4; i += NTHREADS) {
        ((uint4*)Wp2)[i]         = ((const uint4*)g_Whi2)[i];
        ((uint4*)(Wp2 + NW2))[i] = ((const uint4*)g_Wlo2)[i];
    }
    for (int i = tid; i < NW3 / 4; i += NTHREADS) {
        ((uint4*)Wp3)[i]         = ((const uint4*)g_Whi3)[i];
        ((uint4*)(Wp3 + NW3))[i] = ((const uint4*)g_Wlo3)[i];
    }
    for (int i = tid; i < 384; i += NTHREADS) w1p[i] = W1[i];
    if (tid < HID)  bs2[tid] = b2[tid];
    if (tid < OUTD) bs3[tid] = b3[tid];
    __syncthreads();

    for (int tile = blockIdx.x; tile < ntiles; tile += gridDim.x) {
        int node0 = tile * MT;
        if (tid < MT) {
            int node = node0 + tid;
            sb[tid] = (node < N) ? batch[node] : -1;
            sz[tid] = (node < N) ? z[node] : 0;
        }
        for (int idx = tid; idx < 3 * MT; idx += NTHREADS) {
            int g = node0 * 3 + idx;
            spos[idx] = (g < N * 3) ? pos[g] : 0.f;
        }
        __syncthreads();

        // ---- layer 1 into A-fragment layout, bf16 hi/lo packed regs ----
        // vh/vl[f][kb][j]: m-frag f (rows grp*32+f*16 ..), k-block kb,
        // j: 0=(r,k0) 1=(r+8,k0) 2=(r,k0+8) 3=(r+8,k0+8)
        int rb = grp * 32 + (lane >> 2);
        unsigned vh[2][KB16][4], vl[2][KB16][4];
#pragma unroll
        for (int f = 0; f < 2; f++) {
            int r0 = rb + f * 16, r8 = r0 + 8;
            const float* e0 = g_E1 + sz[r0] * HID;
            const float* e8 = g_E1 + sz[r8] * HID;
            float q00 = spos[3 * r0], q01 = spos[3 * r0 + 1], q02 = spos[3 * r0 + 2];
            float q80 = spos[3 * r8], q81 = spos[3 * r8 + 1], q82 = spos[3 * r8 + 2];
#pragma unroll
            for (int kb = 0; kb < KB16; kb++) {
#pragma unroll
                for (int jj = 0; jj < 2; jj++) {
                    int k0 = kb * 16 + cg + jj * 8;
                    float2 eA = *reinterpret_cast<const float2*>(e0 + k0);
                    float2 eB = *reinterpret_cast<const float2*>(e8 + k0);
                    float2 wa = *reinterpret_cast<const float2*>(w1p + k0);
                    float2 wb = *reinterpret_cast<const float2*>(w1p + 128 + k0);
                    float2 wc = *reinterpret_cast<const float2*>(w1p + 256 + k0);
                    float a0 = fmaxf(fmaf(q02, wc.x, fmaf(q01, wb.x, fmaf(q00, wa.x, eA.x))), 0.f);
                    float a1 = fmaxf(fmaf(q02, wc.y, fmaf(q01, wb.y, fmaf(q00, wa.y, eA.y))), 0.f);
                    float c0 = fmaxf(fmaf(q82, wc.x, fmaf(q81, wb.x, fmaf(q80, wa.x, eB.x))), 0.f);
                    float c1 = fmaxf(fmaf(q82, wc.y, fmaf(q81, wb.y, fmaf(q80, wa.y, eB.y))), 0.f);
                    split_pack(a0, a1, vh[f][kb][jj * 2],     vl[f][kb][jj * 2]);
                    split_pack(c0, c1, vh[f][kb][jj * 2 + 1], vl[f][kb][jj * 2 + 1]);
                }
            }
        }

        // ---- layer 2 (N-split): 32 rows x 64 cols per warp ----
        float acc[2][8][4];
#pragma unroll
        for (int f = 0; f < 2; f++)
#pragma unroll
            for (int nb = 0; nb < 8; nb++) {
                int c = (odd * 8 + nb) * 8 + cg;
                acc[f][nb][0] = bs2[c]; acc[f][nb][1] = bs2[c + 1];
                acc[f][nb][2] = bs2[c]; acc[f][nb][3] = bs2[c + 1];
            }
#pragma unroll
        for (int kb = 0; kb < KB16; kb++) {
            const unsigned* whr = Wp2 + (kb * 32 + lane) * WSTR2 + odd * 16;
            const unsigned* wlr = whr + NW2;
#pragma unroll
            for (int np = 0; np < 4; np++) {
                uint4 bh = *reinterpret_cast<const uint4*>(whr + np * 4);
                uint4 bl = *reinterpret_cast<const uint4*>(wlr + np * 4);
#pragma unroll
                for (int f = 0; f < 2; f++) {
                    MMA_BF16(acc[f][2 * np],     vh[f][kb][0], vh[f][kb][1], vh[f][kb][2], vh[f][kb][3], bh.x, bh.y);
                    MMA_BF16(acc[f][2 * np],     vl[f][kb][0], vl[f][kb][1], vl[f][kb][2], vl[f][kb][3], bh.x, bh.y);
                    MMA_BF16(acc[f][2 * np],     vh[f][kb][0], vh[f][kb][1], vh[f][kb][2], vh[f][kb][3], bl.x, bl.y);
                    MMA_BF16(acc[f][2 * np + 1], vh[f][kb][0], vh[f][kb][1], vh[f][kb][2], vh[f][kb][3], bh.z, bh.w);
                    MMA_BF16(acc[f][2 * np + 1], vl[f][kb][0], vl[f][kb][1], vl[f][kb][2], vl[f][kb][3], bh.z, bh.w);
                    MMA_BF16(acc[f][2 * np + 1], vh[f][kb][0], vh[f][kb][1], vh[f][kb][2], vh[f][kb][3], bl.z, bl.w);
                }
            }
        }

        // ---- epilogue l2: relu + split -> layer3 A fragments ----
        unsigned uh[2][4][4], ul[2][4][4];
#pragma unroll
        for (int f = 0; f < 2; f++)
#pragma unroll
            for (int kbl = 0; kbl < 4; kbl++) {
                split_pack(fmaxf(acc[f][2 * kbl][0], 0.f),     fmaxf(acc[f][2 * kbl][1], 0.f),
                           uh[f][kbl][0], ul[f][kbl][0]);
                split_pack(fmaxf(acc[f][2 * kbl][2], 0.f),     fmaxf(acc[f][2 * kbl][3], 0.f),
                           uh[f][kbl][1], ul[f][kbl][1]);
                split_pack(fmaxf(acc[f][2 * kbl + 1][0], 0.f), fmaxf(acc[f][2 * kbl + 1][1], 0.f),
                           uh[f][kbl][2], ul[f][kbl][2]);
                split_pack(fmaxf(acc[f][2 * kbl + 1][2], 0.f), fmaxf(acc[f][2 * kbl + 1][3], 0.f),
                           uh[f][kbl][3], ul[f][kbl][3]);
            }

        // ---- layer 3 (K-split): partial y over k-range odd*64.. ----
        float a3c[2][NB3][4];
#pragma unroll
        for (int f = 0; f < 2; f++)
#pragma unroll
            for (int nb = 0; nb < NB3; nb++) {
                float b0 = odd ? 0.f : bs3[nb * 8 + cg];
                float b1v = odd ? 0.f : bs3[nb * 8 + cg + 1];
                a3c[f][nb][0] = b0; a3c[f][nb][1] = b1v;
                a3c[f][nb][2] = b0; a3c[f][nb][3] = b1v;
            }
#pragma unroll
        for (int kbl = 0; kbl < 4; kbl++) {
            int kbg = odd * 4 + kbl;
            const unsigned* whr = Wp3 + (kbg * 32 + lane) * WSTR3;
            const unsigned* wlr = whr + NW3;
#pragma unroll
            for (int np = 0; np < 4; np++) {
                uint4 bh = *reinterpret_cast<const uint4*>(whr + np * 4);
                uint4 bl = *reinterpret_cast<const uint4*>(wlr + np * 4);
#pragma unroll
                for (int f = 0; f < 2; f++) {
                    MMA_BF16(a3c[f][2 * np],     uh[f][kbl][0], uh[f][kbl][1], uh[f][kbl][2], uh[f][kbl][3], bh.x, bh.y);
                    MMA_BF16(a3c[f][2 * np],     ul[f][kbl][0], ul[f][kbl][1], ul[f][kbl][2], ul[f][kbl][3], bh.x, bh.y);
                    MMA_BF16(a3c[f][2 * np],     uh[f][kbl][0], uh[f][kbl][1], uh[f][kbl][2], uh[f][kbl][3], bl.x, bl.y);
                    MMA_BF16(a3c[f][2 * np + 1], uh[f][kbl][0], uh[f][kbl][1], uh[f][kbl][2], uh[f][kbl][3], bh.z, bh.w);
                    MMA_BF16(a3c[f][2 * np + 1], ul[f][kbl][0], ul[f][kbl][1], ul[f][kbl][2], ul[f][kbl][3], bh.z, bh.w);
                    MMA_BF16(a3c[f][2 * np + 1], uh[f][kbl][0], uh[f][kbl][1], uh[f][kbl][2], uh[f][kbl][3], bl.z, bl.w);
                }
            }
        }

        // ---- exchange K-split partials (in place) ----
        __syncthreads();
        if (odd) {
#pragma unroll
            for (int f = 0; f < 2; f++) {
                int r0 = rb + f * 16, r8 = r0 + 8;
#pragma unroll
                for (int nb = 0; nb < NB3; nb++) {
                    int col = nb * 8 + cg;
                    *reinterpret_cast<float2*>(&xb[r0 * XSTR + col]) =
                        make_float2(a3c[f][nb][0], a3c[f][nb][1]);
                    *reinterpret_cast<float2*>(&xb[r8 * XSTR + col]) =
                        make_float2(a3c[f][nb][2], a3c[f][nb][3]);
                }
            }
        }
        __syncthreads();
        if (!odd) {
#pragma unroll
            for (int f = 0; f < 2; f++) {
                int r0 = rb + f * 16, r8 = r0 + 8;
#pragma unroll
                for (int nb = 0; nb < NB3; nb++) {
                    int col = nb * 8 + cg;
                    float2 x0 = *reinterpret_cast<const float2*>(&xb[r0 * XSTR + col]);
                    float2 x8 = *reinterpret_cast<const float2*>(&xb[r8 * XSTR + col]);
                    *reinterpret_cast<float2*>(&xb[r0 * XSTR + col]) =
                        make_float2(a3c[f][nb][0] + x0.x, a3c[f][nb][1] + x0.y);
                    *reinterpret_cast<float2*>(&xb[r8 * XSTR + col]) =
                        make_float2(a3c[f][nb][2] + x8.x, a3c[f][nb][3] + x8.y);
                }
            }
        }
        __syncthreads();

        // ---- segment reduction (batch sorted): 4 chunks x 32 rows ----
        {
            int col = tid & 63, chunk = tid >> 6;
            int i0 = chunk * 32, i1 = i0 + 32;
            float sum = 0.f; int cur = -1;
            for (int i = i0; i < i1; i++) {
                int b = sb[i];
                if (b != cur) {
                    if (cur >= 0) atomicAdd(&g_accum[cur * OUTD + col], sum);
                    sum = 0.f; cur = b;
                }
                if (b >= 0) sum += xb[i * XSTR + col];
            }
            if (cur >= 0) atomicAdd(&g_accum[cur * OUTD + col], sum);
        }
        if (tid < 4) {
            int i0 = tid * 32, i1 = i0 + 32;
            float c = 0.f; int cur = -1;
            for (int i = i0; i < i1; i++) {
                int b = sb[i];
                if (b != cur) {
                    if (cur >= 0) atomicAdd(&g_cnt[cur], c);
                    c = 0.f; cur = b;
                }
                if (b >= 0) c += 1.f;
            }
            if (cur >= 0) atomicAdd(&g_cnt[cur], c);
        }
        __syncthreads();   // protect sb/sz/spos/xb before next tile
    }
}

__global__ void finalize_kernel(float* __restrict__ out) {
    int idx = blockIdx.x * blockDim.x + threadIdx.x;
    if (idx < NG * OUTD)
        out[idx] = g_accum[idx] / fmaxf(g_cnt[idx >> 6], 1.0f);
}

extern "C" void kernel_launch(void* const* d_in, const int* in_sizes, int n_in,
                              void* d_out, int out_size)
{
    const float* pos   = (const float*)d_in[0];
    const int*   z     = (const int*)  d_in[1];
    const int*   batch = (const int*)  d_in[2];
    const float* emb   = (const float*)d_in[3];
    const float* W1    = (const float*)d_in[4];
    const float* b1    = (const float*)d_in[5];
    const float* W2    = (const float*)d_in[6];
    const float* b2    = (const float*)d_in[7];
    const float* W3    = (const float*)d_in[8];
    const float* b3    = (const float*)d_in[9];

    int N = in_sizes[1];
    int ntiles = (N + MT - 1) / MT;

    size_t smem_bytes = (size_t)(2 * NW2 + 2 * NW3) * 4
                      + (size_t)(MT * XSTR) * 4
                      + (size_t)(HID + OUTD + 384 + 3 * MT) * 4
                      + (size_t)(2 * MT) * 4;
    cudaFuncSetAttribute(gnn_kernel, cudaFuncAttributeMaxDynamicSharedMemorySize,
                         (int)smem_bytes);

    e1_kernel<<<NTYPES, HID>>>(emb, W1, b1);
    permute_w_kernel<<<(KB16 * 32 * NB2 * 2 + 255) / 256, 256>>>(W2, W3);
    zero_kernel<<<(NG * OUTD + 255) / 256, 256>>>();

    gnn_kernel<<<GRID_P, NTHREADS, smem_bytes>>>(pos, z, batch, W1, b2, b3, N, ntiles);

    finalize_kernel<<<(NG * OUTD + 255) / 256, 256>>>((float*)d_out);
}

// round 13
// speedup vs baseline: 7.6073x; 1.2201x over previous
#include <cuda_runtime.h>
#include <cuda_fp16.h>

#define NG      4096
#define OUTD    64
#define HID     128
#define NFEAT   125
#define NTYPES  100
#define MT      128
#define NTHREADS 256
#define GRID_P  152
#define KB16    8
#define NB2     16
#define NB3     8
#define WSTR2   36
#define WSTR3   20
#define NW2     (KB16 * 32 * WSTR2)   // 9216 words per W2 part
#define NW3     (KB16 * 32 * WSTR3)   // 5120 words per W3 part
#define XSTR    66

__device__ float    g_accum[NG * OUTD];
__device__ float    g_cnt[NG];
__device__ float    g_E1[NTYPES * HID];
__device__ unsigned g_Whi2[NW2];
__device__ unsigned g_Wlo2[NW2];
__device__ unsigned g_Whi3[NW3];
__device__ unsigned g_Wlo3[NW3];

// pack two fp32 into fp16x2 (lo -> low half, hi -> high half), one cvt
__device__ __forceinline__ unsigned pack_f16x2(float lo, float hi) {
    unsigned d;
    asm("cvt.rn.f16x2.f32 %0, %1, %2;" : "=r"(d) : "f"(hi), "f"(lo));
    return d;
}

#define MMA_F16(c, a0, a1, a2, a3, b0, b1)                                    \
    asm volatile("mma.sync.aligned.m16n8k16.row.col.f32.f16.f16.f32 "         \
                 "{%0,%1,%2,%3},{%4,%5,%6,%7},{%8,%9},{%0,%1,%2,%3};"         \
                 : "+f"(c[0]), "+f"(c[1]), "+f"(c[2]), "+f"(c[3])             \
                 : "r"(a0), "r"(a1), "r"(a2), "r"(a3), "r"(b0), "r"(b1))

__global__ void e1_kernel(const float* __restrict__ emb,
                          const float* __restrict__ W1,
                          const float* __restrict__ b1) {
    __shared__ float e[NFEAT];
    int t = blockIdx.x, c = threadIdx.x;
    if (c < NFEAT) e[c] = emb[t * NFEAT + c];
    __syncthreads();
    float s = b1[c];
#pragma unroll 5
    for (int d = 0; d < NFEAT; d++)
        s = fmaf(e[d], W1[(3 + d) * HID + c], s);
    g_E1[t * HID + c] = s;
}

__global__ void zero_kernel() {
    int idx = blockIdx.x * blockDim.x + threadIdx.x;
    if (idx < NG * OUTD) g_accum[idx] = 0.0f;
    if (idx < NG)        g_cnt[idx]   = 0.0f;
}

// W fragments: fp16 hi + fp16 lo (lo = fp16(w - fp16(w))), fragment-ordered.
__global__ void permute_w_kernel(const float* __restrict__ W2,
                                 const float* __restrict__ W3) {
    int idx = blockIdx.x * blockDim.x + threadIdx.x;
    if (idx < KB16 * 32 * NB2 * 2) {
        int j    = idx & 1;
        int nb   = (idx >> 1) % NB2;
        int lane = ((idx >> 1) / NB2) & 31;
        int kb   = (idx >> 1) / (NB2 * 32);
        int k0 = kb * 16 + 2 * (lane & 3) + j * 8;
        int n  = nb * 8 + (lane >> 2);
        float wa = W2[k0 * HID + n];
        float wb = W2[(k0 + 1) * HID + n];
        __half ha = __float2half_rn(wa), hb = __float2half_rn(wb);
        __half la = __float2half_rn(wa - __half2float(ha));
        __half lb = __float2half_rn(wb - __half2float(hb));
        int o = (kb * 32 + lane) * WSTR2 + nb * 2 + j;
        g_Whi2[o] = (unsigned)__half_as_ushort(ha) | ((unsigned)__half_as_ushort(hb) << 16);
        g_Wlo2[o] = (unsigned)__half_as_ushort(la) | ((unsigned)__half_as_ushort(lb) << 16);
    }
    if (idx < KB16 * 32 * NB3 * 2) {
        int j    = idx & 1;
        int nb   = (idx >> 1) % NB3;
        int lane = ((idx >> 1) / NB3) & 31;
        int kb   = (idx >> 1) / (NB3 * 32);
        int k0 = kb * 16 + 2 * (lane & 3) + j * 8;
        int n  = nb * 8 + (lane >> 2);
        float wa = W3[k0 * OUTD + n];
        float wb = W3[(k0 + 1) * OUTD + n];
        __half ha = __float2half_rn(wa), hb = __float2half_rn(wb);
        __half la = __float2half_rn(wa - __half2float(ha));
        __half lb = __float2half_rn(wb - __half2float(hb));
        int o = (kb * 32 + lane) * WSTR3 + nb * 2 + j;
        g_Whi3[o] = (unsigned)__half_as_ushort(ha) | ((unsigned)__half_as_ushort(hb) << 16);
        g_Wlo3[o] = (unsigned)__half_as_ushort(la) | ((unsigned)__half_as_ushort(lb) << 16);
    }
}

__global__ void __launch_bounds__(NTHREADS, 1) gnn_kernel(
    const float* __restrict__ pos, const int* __restrict__ z,
    const int* __restrict__ batch, const float* __restrict__ W1,
    const float* __restrict__ b2, const float* __restrict__ b3,
    int N, int ntiles)
{
    extern __shared__ unsigned smem[];
    unsigned* Wp2  = smem;                    // 2*NW2 (hi | lo)
    unsigned* Wp3  = Wp2 + 2 * NW2;           // 2*NW3 (hi | lo)
    float*    xb   = (float*)(Wp3 + 2 * NW3); // MT*XSTR exchange/y
    float*    bs2  = xb + MT * XSTR;          // 128
    float*    bs3  = bs2 + HID;               // 64
    float*    w1p  = bs3 + OUTD;              // 384
    float*    spos = w1p + 384;               // 3*MT
    int*      sb   = (int*)(spos + 3 * MT);   // MT
    int*      sz   = sb + MT;                 // MT

    int tid = threadIdx.x, lane = tid & 31, wid = tid >> 5;
    int grp = wid >> 1;
    int odd = wid & 1;
    int cg  = (lane & 3) * 2;

    for (int i = tid; i < NW2 / 4; i += NTHREADS) {
        ((uint4*)Wp2)[i]         = ((const uint4*)g_Whi2)[i];
        ((uint4*)(Wp2 + NW2))[i] = ((const uint4*)g_Wlo2)[i];
    }
    for (int i = tid; i < NW3 / 4; i += NTHREADS) {
        ((uint4*)Wp3)[i]         = ((const uint4*)g_Whi3)[i];
        ((uint4*)(Wp3 + NW3))[i] = ((const uint4*)g_Wlo3)[i];
    }
    for (int i = tid; i < 384; i += NTHREADS) w1p[i] = W1[i];
    if (tid < HID)  bs2[tid] = b2[tid];
    if (tid < OUTD) bs3[tid] = b3[tid];
    __syncthreads();

    for (int tile = blockIdx.x; tile < ntiles; tile += gridDim.x) {
        int node0 = tile * MT;
        if (tid < MT) {
            int node = node0 + tid;
            sb[tid] = (node < N) ? batch[node] : -1;
            sz[tid] = (node < N) ? z[node] : 0;
        }
        for (int idx = tid; idx < 3 * MT; idx += NTHREADS) {
            int g = node0 * 3 + idx;
            spos[idx] = (g < N * 3) ? pos[g] : 0.f;
        }
        __syncthreads();

        // ---- layer 1 into A-fragment layout, single fp16 packed regs ----
        int rb = grp * 32 + (lane >> 2);
        unsigned vh[2][KB16][4];
#pragma unroll
        for (int f = 0; f < 2; f++) {
            int r0 = rb + f * 16, r8 = r0 + 8;
            const float* e0 = g_E1 + sz[r0] * HID;
            const float* e8 = g_E1 + sz[r8] * HID;
            float q00 = spos[3 * r0], q01 = spos[3 * r0 + 1], q02 = spos[3 * r0 + 2];
            float q80 = spos[3 * r8], q81 = spos[3 * r8 + 1], q82 = spos[3 * r8 + 2];
#pragma unroll
            for (int kb = 0; kb < KB16; kb++) {
#pragma unroll
                for (int jj = 0; jj < 2; jj++) {
                    int k0 = kb * 16 + cg + jj * 8;
                    float2 eA = *reinterpret_cast<const float2*>(e0 + k0);
                    float2 eB = *reinterpret_cast<const float2*>(e8 + k0);
                    float2 wa = *reinterpret_cast<const float2*>(w1p + k0);
                    float2 wb = *reinterpret_cast<const float2*>(w1p + 128 + k0);
                    float2 wc = *reinterpret_cast<const float2*>(w1p + 256 + k0);
                    float a0 = fmaxf(fmaf(q02, wc.x, fmaf(q01, wb.x, fmaf(q00, wa.x, eA.x))), 0.f);
                    float a1 = fmaxf(fmaf(q02, wc.y, fmaf(q01, wb.y, fmaf(q00, wa.y, eA.y))), 0.f);
                    float c0 = fmaxf(fmaf(q82, wc.x, fmaf(q81, wb.x, fmaf(q80, wa.x, eB.x))), 0.f);
                    float c1 = fmaxf(fmaf(q82, wc.y, fmaf(q81, wb.y, fmaf(q80, wa.y, eB.y))), 0.f);
                    vh[f][kb][jj * 2]     = pack_f16x2(a0, a1);
                    vh[f][kb][jj * 2 + 1] = pack_f16x2(c0, c1);
                }
            }
        }

        // ---- layer 2 (N-split): D = A@Wh + A@Wl ----
        float acc[2][8][4];
#pragma unroll
        for (int f = 0; f < 2; f++)
#pragma unroll
            for (int nb = 0; nb < 8; nb++) {
                int c = (odd * 8 + nb) * 8 + cg;
                acc[f][nb][0] = bs2[c]; acc[f][nb][1] = bs2[c + 1];
                acc[f][nb][2] = bs2[c]; acc[f][nb][3] = bs2[c + 1];
            }
#pragma unroll
        for (int kb = 0; kb < KB16; kb++) {
            const unsigned* whr = Wp2 + (kb * 32 + lane) * WSTR2 + odd * 16;
            const unsigned* wlr = whr + NW2;
#pragma unroll
            for (int np = 0; np < 4; np++) {
                uint4 bh = *reinterpret_cast<const uint4*>(whr + np * 4);
                uint4 bl = *reinterpret_cast<const uint4*>(wlr + np * 4);
#pragma unroll
                for (int f = 0; f < 2; f++) {
                    MMA_F16(acc[f][2 * np],     vh[f][kb][0], vh[f][kb][1], vh[f][kb][2], vh[f][kb][3], bh.x, bh.y);
                    MMA_F16(acc[f][2 * np],     vh[f][kb][0], vh[f][kb][1], vh[f][kb][2], vh[f][kb][3], bl.x, bl.y);
                    MMA_F16(acc[f][2 * np + 1], vh[f][kb][0], vh[f][kb][1], vh[f][kb][2], vh[f][kb][3], bh.z, bh.w);
                    MMA_F16(acc[f][2 * np + 1], vh[f][kb][0], vh[f][kb][1], vh[f][kb][2], vh[f][kb][3], bl.z, bl.w);
                }
            }
        }

        // ---- epilogue l2: relu + pack fp16 -> layer3 A fragments ----
        unsigned uh[2][4][4];
#pragma unroll
        for (int f = 0; f < 2; f++)
#pragma unroll
            for (int kbl = 0; kbl < 4; kbl++) {
                uh[f][kbl][0] = pack_f16x2(fmaxf(acc[f][2 * kbl][0], 0.f),
                                           fmaxf(acc[f][2 * kbl][1], 0.f));
                uh[f][kbl][1] = pack_f16x2(fmaxf(acc[f][2 * kbl][2], 0.f),
                                           fmaxf(acc[f][2 * kbl][3], 0.f));
                uh[f][kbl][2] = pack_f16x2(fmaxf(acc[f][2 * kbl + 1][0], 0.f),
                                           fmaxf(acc[f][2 * kbl + 1][1], 0.f));
                uh[f][kbl][3] = pack_f16x2(fmaxf(acc[f][2 * kbl + 1][2], 0.f),
                                           fmaxf(acc[f][2 * kbl + 1][3], 0.f));
            }

        // ---- layer 3 (K-split): partial y over k-range odd*64.. ----
        float a3c[2][NB3][4];
#pragma unroll
        for (int f = 0; f < 2; f++)
#pragma unroll
            for (int nb = 0; nb < NB3; nb++) {
                float b0 = odd ? 0.f : bs3[nb * 8 + cg];
                float b1v = odd ? 0.f : bs3[nb * 8 + cg + 1];
                a3c[f][nb][0] = b0; a3c[f][nb][1] = b1v;
                a3c[f][nb][2] = b0; a3c[f][nb][3] = b1v;
            }
#pragma unroll
        for (int kbl = 0; kbl < 4; kbl++) {
            int kbg = odd * 4 + kbl;
            const unsigned* whr = Wp3 + (kbg * 32 + lane) * WSTR3;
            const unsigned* wlr = whr + NW3;
#pragma unroll
            for (int np = 0; np < 4; np++) {
                uint4 bh = *reinterpret_cast<const uint4*>(whr + np * 4);
                uint4 bl = *reinterpret_cast<const uint4*>(wlr + np * 4);
#pragma unroll
                for (int f = 0; f < 2; f++) {
                    MMA_F16(a3c[f][2 * np],     uh[f][kbl][0], uh[f][kbl][1], uh[f][kbl][2], uh[f][kbl][3], bh.x, bh.y);
                    MMA_F16(a3c[f][2 * np],     uh[f][kbl][0], uh[f][kbl][1], uh[f][kbl][2], uh[f][kbl][3], bl.x, bl.y);
                    MMA_F16(a3c[f][2 * np + 1], uh[f][kbl][0], uh[f][kbl][1], uh[f][kbl][2], uh[f][kbl][3], bh.z, bh.w);
                    MMA_F16(a3c[f][2 * np + 1], uh[f][kbl][0], uh[f][kbl][1], uh[f][kbl][2], uh[f][kbl][3], bl.z, bl.w);
                }
            }
        }

        // ---- exchange K-split partials (in place) ----
        __syncthreads();
        if (odd) {
#pragma unroll
            for (int f = 0; f < 2; f++) {
                int r0 = rb + f * 16, r8 = r0 + 8;
#pragma unroll
                for (int nb = 0; nb < NB3; nb++) {
                    int col = nb * 8 + cg;
                    *reinterpret_cast<float2*>(&xb[r0 * XSTR + col]) =
                        make_float2(a3c[f][nb][0], a3c[f][nb][1]);
                    *reinterpret_cast<float2*>(&xb[r8 * XSTR + col]) =
                        make_float2(a3c[f][nb][2], a3c[f][nb][3]);
                }
            }
        }
        __syncthreads();
        if (!odd) {
#pragma unroll
            for (int f = 0; f < 2; f++) {
                int r0 = rb + f * 16, r8 = r0 + 8;
#pragma unroll
                for (int nb = 0; nb < NB3; nb++) {
                    int col = nb * 8 + cg;
                    float2 x0 = *reinterpret_cast<const float2*>(&xb[r0 * XSTR + col]);
                    float2 x8 = *reinterpret_cast<const float2*>(&xb[r8 * XSTR + col]);
                    *reinterpret_cast<float2*>(&xb[r0 * XSTR + col]) =
                        make_float2(a3c[f][nb][0] + x0.x, a3c[f][nb][1] + x0.y);
                    *reinterpret_cast<float2*>(&xb[r8 * XSTR + col]) =
                        make_float2(a3c[f][nb][2] + x8.x, a3c[f][nb][3] + x8.y);
                }
            }
        }
        __syncthreads();

        // ---- segment reduction (batch sorted) ----
        {
            int col = tid & 63, chunk = tid >> 6;
            int i0 = chunk * 32, i1 = i0 + 32;
            float sum = 0.f; int cur = -1;
            for (int i = i0; i < i1; i++) {
                int b = sb[i];
                if (b != cur) {
                    if (cur >= 0) atomicAdd(&g_accum[cur * OUTD + col], sum);
                    sum = 0.f; cur = b;
                }
                if (b >= 0) sum += xb[i * XSTR + col];
            }
            if (cur >= 0) atomicAdd(&g_accum[cur * OUTD + col], sum);
        }
        if (tid < 4) {
            int i0 = tid * 32, i1 = i0 + 32;
            float c = 0.f; int cur = -1;
            for (int i = i0; i < i1; i++) {
                int b = sb[i];
                if (b != cur) {
                    if (cur >= 0) atomicAdd(&g_cnt[cur], c);
                    c = 0.f; cur = b;
                }
                if (b >= 0) c += 1.f;
            }
            if (cur >= 0) atomicAdd(&g_cnt[cur], c);
        }
        __syncthreads();
    }
}

__global__ void finalize_kernel(float* __restrict__ out) {
    int idx = blockIdx.x * blockDim.x + threadIdx.x;
    if (idx < NG * OUTD)
        out[idx] = g_accum[idx] / fmaxf(g_cnt[idx >> 6], 1.0f);
}

extern "C" void kernel_launch(void* const* d_in, const int* in_sizes, int n_in,
                              void* d_out, int out_size)
{
    const float* pos   = (const float*)d_in[0];
    const int*   z     = (const int*)  d_in[1];
    const int*   batch = (const int*)  d_in[2];
    const float* emb   = (const float*)d_in[3];
    const float* W1    = (const float*)d_in[4];
    const float* b1    = (const float*)d_in[5];
    const float* W2    = (const float*)d_in[6];
    const float* b2    = (const float*)d_in[7];
    const float* W3    = (const float*)d_in[8];
    const float* b3    = (const float*)d_in[9];

    int N = in_sizes[1];
    int ntiles = (N + MT - 1) / MT;

    size_t smem_bytes = (size_t)(2 * NW2 + 2 * NW3) * 4
                      + (size_t)(MT * XSTR) * 4
                      + (size_t)(HID + OUTD + 384 + 3 * MT) * 4
                      + (size_t)(2 * MT) * 4;
    cudaFuncSetAttribute(gnn_kernel, cudaFuncAttributeMaxDynamicSharedMemorySize,
                         (int)smem_bytes);

    e1_kernel<<<NTYPES, HID>>>(emb, W1, b1);
    permute_w_kernel<<<(KB16 * 32 * NB2 * 2 + 255) / 256, 256>>>(W2, W3);
    zero_kernel<<<(NG * OUTD + 255) / 256, 256>>>();

    gnn_kernel<<<GRID_P, NTHREADS, smem_bytes>>>(pos, z, batch, W1, b2, b3, N, ntiles);

    finalize_kernel<<<(NG * OUTD + 255) / 256, 256>>>((float*)d_out);
}

// round 14
// speedup vs baseline: 8.6651x; 1.1391x over previous
#include <cuda_runtime.h>
#include <cuda_fp16.h>

#define NG      4096
#define OUTD    64
#define HID     128
#define NFEAT   125
#define NTYPES  100
#define MT      128
#define NTHREADS 256
#define GRID_P  152
#define KB16    8
#define NB2     16
#define NB3     8
#define WSTR2   36
#define WSTR3   20
#define NW2     (KB16 * 32 * WSTR2)   // 9216 words (W2 fragments)
#define NW3     (KB16 * 32 * WSTR3)   // 5120 words (W3 fragments)
#define XSTR    66

__device__ float    g_accum[NG * OUTD];
__device__ float    g_cnt[NG];
__device__ float    g_E1[NTYPES * HID];
__device__ unsigned g_W2p[NW2];
__device__ unsigned g_W3p[NW3];

__device__ __forceinline__ unsigned pack_f16x2(float lo, float hi) {
    unsigned d;
    asm("cvt.rn.f16x2.f32 %0, %1, %2;" : "=r"(d) : "f"(hi), "f"(lo));
    return d;
}

#define MMA_F16(c, a0, a1, a2, a3, b0, b1)                                    \
    asm volatile("mma.sync.aligned.m16n8k16.row.col.f32.f16.f16.f32 "         \
                 "{%0,%1,%2,%3},{%4,%5,%6,%7},{%8,%9},{%0,%1,%2,%3};"         \
                 : "+f"(c[0]), "+f"(c[1]), "+f"(c[2]), "+f"(c[3])             \
                 : "r"(a0), "r"(a1), "r"(a2), "r"(a3), "r"(b0), "r"(b1))

__global__ void e1_kernel(const float* __restrict__ emb,
                          const float* __restrict__ W1,
                          const float* __restrict__ b1) {
    __shared__ float e[NFEAT];
    int t = blockIdx.x, c = threadIdx.x;
    if (c < NFEAT) e[c] = emb[t * NFEAT + c];
    __syncthreads();
    float s = b1[c];
#pragma unroll 5
    for (int d = 0; d < NFEAT; d++)
        s = fmaf(e[d], W1[(3 + d) * HID + c], s);
    g_E1[t * HID + c] = s;
}

__global__ void zero_kernel() {
    int idx = blockIdx.x * blockDim.x + threadIdx.x;
    if (idx < NG * OUTD) g_accum[idx] = 0.0f;
    if (idx < NG)        g_cnt[idx]   = 0.0f;
}

// W fragments: single fp16, fragment-ordered.
__global__ void permute_w_kernel(const float* __restrict__ W2,
                                 const float* __restrict__ W3) {
    int idx = blockIdx.x * blockDim.x + threadIdx.x;
    if (idx < KB16 * 32 * NB2 * 2) {
        int j    = idx & 1;
        int nb   = (idx >> 1) % NB2;
        int lane = ((idx >> 1) / NB2) & 31;
        int kb   = (idx >> 1) / (NB2 * 32);
        int k0 = kb * 16 + 2 * (lane & 3) + j * 8;
        int n  = nb * 8 + (lane >> 2);
        __half ha = __float2half_rn(W2[k0 * HID + n]);
        __half hb = __float2half_rn(W2[(k0 + 1) * HID + n]);
        g_W2p[(kb * 32 + lane) * WSTR2 + nb * 2 + j] =
            (unsigned)__half_as_ushort(ha) | ((unsigned)__half_as_ushort(hb) << 16);
    }
    if (idx < KB16 * 32 * NB3 * 2) {
        int j    = idx & 1;
        int nb   = (idx >> 1) % NB3;
        int lane = ((idx >> 1) / NB3) & 31;
        int kb   = (idx >> 1) / (NB3 * 32);
        int k0 = kb * 16 + 2 * (lane & 3) + j * 8;
        int n  = nb * 8 + (lane >> 2);
        __half ha = __float2half_rn(W3[k0 * OUTD + n]);
        __half hb = __float2half_rn(W3[(k0 + 1) * OUTD + n]);
        g_W3p[(kb * 32 + lane) * WSTR3 + nb * 2 + j] =
            (unsigned)__half_as_ushort(ha) | ((unsigned)__half_as_ushort(hb) << 16);
    }
}

__global__ void __launch_bounds__(NTHREADS, 1) gnn_kernel(
    const float* __restrict__ pos, const int* __restrict__ z,
    const int* __restrict__ batch, const float* __restrict__ W1,
    const float* __restrict__ b2, const float* __restrict__ b3,
    int N, int ntiles)
{
    extern __shared__ unsigned smem[];
    unsigned* Wp2  = smem;                    // NW2
    unsigned* Wp3  = Wp2 + NW2;               // NW3
    float*    xb   = (float*)(Wp3 + NW3);     // MT*XSTR exchange/y
    float*    bs2  = xb + MT * XSTR;          // 128
    float*    bs3  = bs2 + HID;               // 64
    float*    w1p  = bs3 + OUTD;              // 384
    float*    spos = w1p + 384;               // 3*MT
    int*      sb   = (int*)(spos + 3 * MT);   // MT
    int*      sz   = sb + MT;                 // MT

    int tid = threadIdx.x, lane = tid & 31, wid = tid >> 5;
    int grp = wid >> 1;
    int odd = wid & 1;
    int cg  = (lane & 3) * 2;

    for (int i = tid; i < NW2 / 4; i += NTHREADS)
        ((uint4*)Wp2)[i] = ((const uint4*)g_W2p)[i];
    for (int i = tid; i < NW3 / 4; i += NTHREADS)
        ((uint4*)Wp3)[i] = ((const uint4*)g_W3p)[i];
    for (int i = tid; i < 384; i += NTHREADS) w1p[i] = W1[i];
    if (tid < HID)  bs2[tid] = b2[tid];
    if (tid < OUTD) bs3[tid] = b3[tid];
    __syncthreads();

    for (int tile = blockIdx.x; tile < ntiles; tile += gridDim.x) {
        int node0 = tile * MT;
        if (tid < MT) {
            int node = node0 + tid;
            sb[tid] = (node < N) ? batch[node] : -1;
            sz[tid] = (node < N) ? z[node] : 0;
        }
        for (int idx = tid; idx < 3 * MT; idx += NTHREADS) {
            int g = node0 * 3 + idx;
            spos[idx] = (g < N * 3) ? pos[g] : 0.f;
        }
        __syncthreads();

        // ---- layer 1 into A-fragment layout, fp16 packed regs ----
        int rb = grp * 32 + (lane >> 2);
        unsigned vh[2][KB16][4];
#pragma unroll
        for (int f = 0; f < 2; f++) {
            int r0 = rb + f * 16, r8 = r0 + 8;
            const float* e0 = g_E1 + sz[r0] * HID;
            const float* e8 = g_E1 + sz[r8] * HID;
            float q00 = spos[3 * r0], q01 = spos[3 * r0 + 1], q02 = spos[3 * r0 + 2];
            float q80 = spos[3 * r8], q81 = spos[3 * r8 + 1], q82 = spos[3 * r8 + 2];
#pragma unroll
            for (int kb = 0; kb < KB16; kb++) {
#pragma unroll
                for (int jj = 0; jj < 2; jj++) {
                    int k0 = kb * 16 + cg + jj * 8;
                    float2 eA = *reinterpret_cast<const float2*>(e0 + k0);
                    float2 eB = *reinterpret_cast<const float2*>(e8 + k0);
                    float2 wa = *reinterpret_cast<const float2*>(w1p + k0);
                    float2 wb = *reinterpret_cast<const float2*>(w1p + 128 + k0);
                    float2 wc = *reinterpret_cast<const float2*>(w1p + 256 + k0);
                    float a0 = fmaxf(fmaf(q02, wc.x, fmaf(q01, wb.x, fmaf(q00, wa.x, eA.x))), 0.f);
                    float a1 = fmaxf(fmaf(q02, wc.y, fmaf(q01, wb.y, fmaf(q00, wa.y, eA.y))), 0.f);
                    float c0 = fmaxf(fmaf(q82, wc.x, fmaf(q81, wb.x, fmaf(q80, wa.x, eB.x))), 0.f);
                    float c1 = fmaxf(fmaf(q82, wc.y, fmaf(q81, wb.y, fmaf(q80, wa.y, eB.y))), 0.f);
                    vh[f][kb][jj * 2]     = pack_f16x2(a0, a1);
                    vh[f][kb][jj * 2 + 1] = pack_f16x2(c0, c1);
                }
            }
        }

        // ---- layer 2 (N-split): D = A@W ----
        float acc[2][8][4];
#pragma unroll
        for (int f = 0; f < 2; f++)
#pragma unroll
            for (int nb = 0; nb < 8; nb++) {
                int c = (odd * 8 + nb) * 8 + cg;
                acc[f][nb][0] = bs2[c]; acc[f][nb][1] = bs2[c + 1];
                acc[f][nb][2] = bs2[c]; acc[f][nb][3] = bs2[c + 1];
            }
#pragma unroll
        for (int kb = 0; kb < KB16; kb++) {
            const unsigned* whr = Wp2 + (kb * 32 + lane) * WSTR2 + odd * 16;
#pragma unroll
            for (int np = 0; np < 4; np++) {
                uint4 bh = *reinterpret_cast<const uint4*>(whr + np * 4);
#pragma unroll
                for (int f = 0; f < 2; f++) {
                    MMA_F16(acc[f][2 * np],     vh[f][kb][0], vh[f][kb][1], vh[f][kb][2], vh[f][kb][3], bh.x, bh.y);
                    MMA_F16(acc[f][2 * np + 1], vh[f][kb][0], vh[f][kb][1], vh[f][kb][2], vh[f][kb][3], bh.z, bh.w);
                }
            }
        }

        // ---- epilogue l2: relu + pack fp16 -> layer3 A fragments ----
        unsigned uh[2][4][4];
#pragma unroll
        for (int f = 0; f < 2; f++)
#pragma unroll
            for (int kbl = 0; kbl < 4; kbl++) {
                uh[f][kbl][0] = pack_f16x2(fmaxf(acc[f][2 * kbl][0], 0.f),
                                           fmaxf(acc[f][2 * kbl][1], 0.f));
                uh[f][kbl][1] = pack_f16x2(fmaxf(acc[f][2 * kbl][2], 0.f),
                                           fmaxf(acc[f][2 * kbl][3], 0.f));
                uh[f][kbl][2] = pack_f16x2(fmaxf(acc[f][2 * kbl + 1][0], 0.f),
                                           fmaxf(acc[f][2 * kbl + 1][1], 0.f));
                uh[f][kbl][3] = pack_f16x2(fmaxf(acc[f][2 * kbl + 1][2], 0.f),
                                           fmaxf(acc[f][2 * kbl + 1][3], 0.f));
            }

        // ---- layer 3 (K-split): partial y over k-range odd*64.. ----
        float a3c[2][NB3][4];
#pragma unroll
        for (int f = 0; f < 2; f++)
#pragma unroll
            for (int nb = 0; nb < NB3; nb++) {
                float b0 = odd ? 0.f : bs3[nb * 8 + cg];
                float b1v = odd ? 0.f : bs3[nb * 8 + cg + 1];
                a3c[f][nb][0] = b0; a3c[f][nb][1] = b1v;
                a3c[f][nb][2] = b0; a3c[f][nb][3] = b1v;
            }
#pragma unroll
        for (int kbl = 0; kbl < 4; kbl++) {
            int kbg = odd * 4 + kbl;
            const unsigned* whr = Wp3 + (kbg * 32 + lane) * WSTR3;
#pragma unroll
            for (int np = 0; np < 4; np++) {
                uint4 bh = *reinterpret_cast<const uint4*>(whr + np * 4);
#pragma unroll
                for (int f = 0; f < 2; f++) {
                    MMA_F16(a3c[f][2 * np],     uh[f][kbl][0], uh[f][kbl][1], uh[f][kbl][2], uh[f][kbl][3], bh.x, bh.y);
                    MMA_F16(a3c[f][2 * np + 1], uh[f][kbl][0], uh[f][kbl][1], uh[f][kbl][2], uh[f][kbl][3], bh.z, bh.w);
                }
            }
        }

        // ---- exchange K-split partials (in place) ----
        __syncthreads();
        if (odd) {
#pragma unroll
            for (int f = 0; f < 2; f++) {
                int r0 = rb + f * 16, r8 = r0 + 8;
#pragma unroll
                for (int nb = 0; nb < NB3; nb++) {
                    int col = nb * 8 + cg;
                    *reinterpret_cast<float2*>(&xb[r0 * XSTR + col]) =
                        make_float2(a3c[f][nb][0], a3c[f][nb][1]);
                    *reinterpret_cast<float2*>(&xb[r8 * XSTR + col]) =
                        make_float2(a3c[f][nb][2], a3c[f][nb][3]);
                }
            }
        }
        __syncthreads();
        if (!odd) {
#pragma unroll
            for (int f = 0; f < 2; f++) {
                int r0 = rb + f * 16, r8 = r0 + 8;
#pragma unroll
                for (int nb = 0; nb < NB3; nb++) {
                    int col = nb * 8 + cg;
                    float2 x0 = *reinterpret_cast<const float2*>(&xb[r0 * XSTR + col]);
                    float2 x8 = *reinterpret_cast<const float2*>(&xb[r8 * XSTR + col]);
                    *reinterpret_cast<float2*>(&xb[r0 * XSTR + col]) =
                        make_float2(a3c[f][nb][0] + x0.x, a3c[f][nb][1] + x0.y);
                    *reinterpret_cast<float2*>(&xb[r8 * XSTR + col]) =
                        make_float2(a3c[f][nb][2] + x8.x, a3c[f][nb][3] + x8.y);
                }
            }
        }
        __syncthreads();

        // ---- segment reduction (batch sorted) ----
        {
            int col = tid & 63, chunk = tid >> 6;
            int i0 = chunk * 32, i1 = i0 + 32;
            float sum = 0.f; int cur = -1;
            for (int i = i0; i < i1; i++) {
                int b = sb[i];
                if (b != cur) {
                    if (cur >= 0) atomicAdd(&g_accum[cur * OUTD + col], sum);
                    sum = 0.f; cur = b;
                }
                if (b >= 0) sum += xb[i * XSTR + col];
            }
            if (cur >= 0) atomicAdd(&g_accum[cur * OUTD + col], sum);
        }
        if (tid < 4) {
            int i0 = tid * 32, i1 = i0 + 32;
            float c = 0.f; int cur = -1;
            for (int i = i0; i < i1; i++) {
                int b = sb[i];
                if (b != cur) {
                    if (cur >= 0) atomicAdd(&g_cnt[cur], c);
                    c = 0.f; cur = b;
                }
                if (b >= 0) c += 1.f;
            }
            if (cur >= 0) atomicAdd(&g_cnt[cur], c);
        }
        __syncthreads();
    }
}

__global__ void finalize_kernel(float* __restrict__ out) {
    int idx = blockIdx.x * blockDim.x + threadIdx.x;
    if (idx < NG * OUTD)
        out[idx] = g_accum[idx] / fmaxf(g_cnt[idx >> 6], 1.0f);
}

extern "C" void kernel_launch(void* const* d_in, const int* in_sizes, int n_in,
                              void* d_out, int out_size)
{
    const float* pos   = (const float*)d_in[0];
    const int*   z     = (const int*)  d_in[1];
    const int*   batch = (const int*)  d_in[2];
    const float* emb   = (const float*)d_in[3];
    const float* W1    = (const float*)d_in[4];
    const float* b1    = (const float*)d_in[5];
    const float* W2    = (const float*)d_in[6];
    const float* b2    = (const float*)d_in[7];
    const float* W3    = (const float*)d_in[8];
    const float* b3    = (const float*)d_in[9];

    int N = in_sizes[1];
    int ntiles = (N + MT - 1) / MT;

    size_t smem_bytes = (size_t)(NW2 + NW3) * 4
                      + (size_t)(MT * XSTR) * 4
                      + (size_t)(HID + OUTD + 384 + 3 * MT) * 4
                      + (size_t)(2 * MT) * 4;
    cudaFuncSetAttribute(gnn_kernel, cudaFuncAttributeMaxDynamicSharedMemorySize,
                         (int)smem_bytes);

    e1_kernel<<<NTYPES, HID>>>(emb, W1, b1);
    permute_w_kernel<<<(KB16 * 32 * NB2 * 2 + 255) / 256, 256>>>(W2, W3);
    zero_kernel<<<(NG * OUTD + 255) / 256, 256>>>();

    gnn_kernel<<<GRID_P, NTHREADS, smem_bytes>>>(pos, z, batch, W1, b2, b3, N, ntiles);

    finalize_kernel<<<(NG * OUTD + 255) / 256, 256>>>((float*)d_out);
}

// round 16
// speedup vs baseline: 9.9579x; 1.1492x over previous
#include <cuda_runtime.h>
#include <cuda_fp16.h>

#define NG      4096
#define OUTD    64
#define HID     128
#define NFEAT   125
#define NTYPES  100
#define MT      128
#define NTHREADS 256
#define GRID_P  304
#define KB16    8
#define NB3     8
#define WSTR2   36
#define WSTR3   20
#define NW2     (KB16 * 32 * WSTR2)   // 9216 words (W2 fragments)
#define NW3     (KB16 * 32 * WSTR3)   // 5120 words (W3 fragments)
#define XSTR    66

__device__ float    g_accum[NG * OUTD];
__device__ float    g_cnt[NG];
__device__ unsigned g_E1h[NTYPES * 64];   // E1 rows packed fp16x2
__device__ unsigned g_W2p[NW2];
__device__ unsigned g_W3p[NW3];

__device__ __forceinline__ unsigned pack_f16x2(float lo, float hi) {
    unsigned d;
    asm("cvt.rn.f16x2.f32 %0, %1, %2;" : "=r"(d) : "f"(hi), "f"(lo));
    return d;
}
__device__ __forceinline__ __half2 u2h2(unsigned u) {
    return *reinterpret_cast<const __half2*>(&u);
}
__device__ __forceinline__ unsigned h22u(__half2 h) {
    return *reinterpret_cast<const unsigned*>(&h);
}

#define MMA_F16(c, a0, a1, a2, a3, b0, b1)                                    \
    asm volatile("mma.sync.aligned.m16n8k16.row.col.f32.f16.f16.f32 "         \
                 "{%0,%1,%2,%3},{%4,%5,%6,%7},{%8,%9},{%0,%1,%2,%3};"         \
                 : "+f"(c[0]), "+f"(c[1]), "+f"(c[2]), "+f"(c[3])             \
                 : "r"(a0), "r"(a1), "r"(a2), "r"(a3), "r"(b0), "r"(b1))

// E1[t][c] = b1[c] + sum_d emb[t][d]*W1[3+d][c]  (fp32), packed to fp16x2
__global__ void e1_kernel(const float* __restrict__ emb,
                          const float* __restrict__ W1,
                          const float* __restrict__ b1) {
    __shared__ float e[NFEAT];
    __shared__ float col[HID];
    int t = blockIdx.x, c = threadIdx.x;
    if (c < NFEAT) e[c] = emb[t * NFEAT + c];
    __syncthreads();
    float s = b1[c];
#pragma unroll 5
    for (int d = 0; d < NFEAT; d++)
        s = fmaf(e[d], W1[(3 + d) * HID + c], s);
    col[c] = s;
    __syncthreads();
    if (c < 64)
        g_E1h[t * 64 + c] = pack_f16x2(col[2 * c], col[2 * c + 1]);
}

__global__ void zero_kernel() {
    int idx = blockIdx.x * blockDim.x + threadIdx.x;
    if (idx < NG * OUTD) g_accum[idx] = 0.0f;
    if (idx < NG)        g_cnt[idx]   = 0.0f;
}

// W fragments: single fp16, fragment-ordered.
__global__ void permute_w_kernel(const float* __restrict__ W2,
                                 const float* __restrict__ W3) {
    int idx = blockIdx.x * blockDim.x + threadIdx.x;
    if (idx < KB16 * 32 * 16 * 2) {
        int j    = idx & 1;
        int nb   = (idx >> 1) % 16;
        int lane = ((idx >> 1) / 16) & 31;
        int kb   = (idx >> 1) / (16 * 32);
        int k0 = kb * 16 + 2 * (lane & 3) + j * 8;
        int n  = nb * 8 + (lane >> 2);
        g_W2p[(kb * 32 + lane) * WSTR2 + nb * 2 + j] =
            pack_f16x2(W2[k0 * HID + n], W2[(k0 + 1) * HID + n]);
    }
    if (idx < KB16 * 32 * NB3 * 2) {
        int j    = idx & 1;
        int nb   = (idx >> 1) % NB3;
        int lane = ((idx >> 1) / NB3) & 31;
        int kb   = (idx >> 1) / (NB3 * 32);
        int k0 = kb * 16 + 2 * (lane & 3) + j * 8;
        int n  = nb * 8 + (lane >> 2);
        g_W3p[(kb * 32 + lane) * WSTR3 + nb * 2 + j] =
            pack_f16x2(W3[k0 * OUTD + n], W3[(k0 + 1) * OUTD + n]);
    }
}

__global__ void __launch_bounds__(NTHREADS, 2) gnn_kernel(
    const float* __restrict__ pos, const int* __restrict__ z,
    const int* __restrict__ batch, const float* __restrict__ W1,
    const float* __restrict__ b2, const float* __restrict__ b3,
    int N, int ntiles)
{
    extern __shared__ unsigned smem[];
    unsigned* Wp2  = smem;                    // NW2
    unsigned* Wp3  = Wp2 + NW2;               // NW3
    float*    xb   = (float*)(Wp3 + NW3);     // MT*XSTR exchange/y
    float*    bs2  = xb + MT * XSTR;          // 128
    float*    bs3  = bs2 + HID;               // 64
    unsigned* w1h  = (unsigned*)(bs3 + OUTD); // 192 (fp16x2 W1 rows 0..2)
    float*    spos = (float*)(w1h + 192);     // 3*MT
    int*      sb   = (int*)(spos + 3 * MT);   // MT
    int*      sz   = sb + MT;                 // MT

    int tid = threadIdx.x, lane = tid & 31, wid = tid >> 5;
    int grp = wid >> 1;
    int odd = wid & 1;
    int cg  = (lane & 3) * 2;

    for (int i = tid; i < NW2 / 4; i += NTHREADS)
        ((uint4*)Wp2)[i] = ((const uint4*)g_W2p)[i];
    for (int i = tid; i < NW3 / 4; i += NTHREADS)
        ((uint4*)Wp3)[i] = ((const uint4*)g_W3p)[i];
    if (tid < 192) {
        int row = tid / 64, c2 = tid % 64;
        w1h[tid] = pack_f16x2(W1[row * HID + 2 * c2], W1[row * HID + 2 * c2 + 1]);
    }
    if (tid < HID)  bs2[tid] = b2[tid];
    if (tid < OUTD) bs3[tid] = b3[tid];
    __syncthreads();

    const __half2 h2z = __float2half2_rn(0.f);

    for (int tile = blockIdx.x; tile < ntiles; tile += gridDim.x) {
        int node0 = tile * MT;
        if (tid < MT) {
            int node = node0 + tid;
            sb[tid] = (node < N) ? batch[node] : -1;
            sz[tid] = (node < N) ? z[node] : 0;
        }
        for (int idx = tid; idx < 3 * MT; idx += NTHREADS) {
            int g = node0 * 3 + idx;
            spos[idx] = (g < N * 3) ? pos[g] : 0.f;
        }
        __syncthreads();

        int rbq = grp * 32 + (lane >> 2);

#pragma unroll
        for (int f = 0; f < 2; f++) {
            int r0 = rbq + f * 16, r8 = r0 + 8;

            // ---- layer 1 (half2): vh = relu(E1h[z] + pos@W1h) ----
            const unsigned* e0 = g_E1h + sz[r0] * 64;
            const unsigned* e8 = g_E1h + sz[r8] * 64;
            __half2 pa0 = __float2half2_rn(spos[3 * r0]);
            __half2 pa1 = __float2half2_rn(spos[3 * r0 + 1]);
            __half2 pa2 = __float2half2_rn(spos[3 * r0 + 2]);
            __half2 pb0 = __float2half2_rn(spos[3 * r8]);
            __half2 pb1 = __float2half2_rn(spos[3 * r8 + 1]);
            __half2 pb2 = __float2half2_rn(spos[3 * r8 + 2]);

            unsigned vh[KB16][4];
#pragma unroll
            for (int kb = 0; kb < KB16; kb++) {
#pragma unroll
                for (int jj = 0; jj < 2; jj++) {
                    int c2 = kb * 8 + (lane & 3) + jj * 4;
                    __half2 wa = u2h2(w1h[c2]);
                    __half2 wb = u2h2(w1h[64 + c2]);
                    __half2 wc = u2h2(w1h[128 + c2]);
                    __half2 eA = u2h2(e0[c2]);
                    __half2 eB = u2h2(e8[c2]);
                    __half2 vA = __hfma2(pa2, wc, __hfma2(pa1, wb, __hfma2(pa0, wa, eA)));
                    __half2 vB = __hfma2(pb2, wc, __hfma2(pb1, wb, __hfma2(pb0, wa, eB)));
                    vh[kb][jj * 2]     = h22u(__hmax2(vA, h2z));
                    vh[kb][jj * 2 + 1] = h22u(__hmax2(vB, h2z));
                }
            }

            // ---- layer 2 (N-split) ----
            float acc[8][4];
#pragma unroll
            for (int nb = 0; nb < 8; nb++) {
                int c = (odd * 8 + nb) * 8 + cg;
                acc[nb][0] = bs2[c]; acc[nb][1] = bs2[c + 1];
                acc[nb][2] = bs2[c]; acc[nb][3] = bs2[c + 1];
            }
#pragma unroll
            for (int kb = 0; kb < KB16; kb++) {
                const unsigned* whr = Wp2 + (kb * 32 + lane) * WSTR2 + odd * 16;
#pragma unroll
                for (int np = 0; np < 4; np++) {
                    uint4 bh = *reinterpret_cast<const uint4*>(whr + np * 4);
                    MMA_F16(acc[2 * np],     vh[kb][0], vh[kb][1], vh[kb][2], vh[kb][3], bh.x, bh.y);
                    MMA_F16(acc[2 * np + 1], vh[kb][0], vh[kb][1], vh[kb][2], vh[kb][3], bh.z, bh.w);
                }
            }

            // ---- epilogue l2: relu + pack -> layer3 A fragments ----
            unsigned uh[4][4];
#pragma unroll
            for (int kbl = 0; kbl < 4; kbl++) {
                uh[kbl][0] = pack_f16x2(fmaxf(acc[2 * kbl][0], 0.f),
                                        fmaxf(acc[2 * kbl][1], 0.f));
                uh[kbl][1] = pack_f16x2(fmaxf(acc[2 * kbl][2], 0.f),
                                        fmaxf(acc[2 * kbl][3], 0.f));
                uh[kbl][2] = pack_f16x2(fmaxf(acc[2 * kbl + 1][0], 0.f),
                                        fmaxf(acc[2 * kbl + 1][1], 0.f));
                uh[kbl][3] = pack_f16x2(fmaxf(acc[2 * kbl + 1][2], 0.f),
                                        fmaxf(acc[2 * kbl + 1][3], 0.f));
            }

            // ---- layer 3 (K-split) ----
            float a3c[NB3][4];
#pragma unroll
            for (int nb = 0; nb < NB3; nb++) {
                float b0 = odd ? 0.f : bs3[nb * 8 + cg];
                float b1v = odd ? 0.f : bs3[nb * 8 + cg + 1];
                a3c[nb][0] = b0; a3c[nb][1] = b1v;
                a3c[nb][2] = b0; a3c[nb][3] = b1v;
            }
#pragma unroll
            for (int kbl = 0; kbl < 4; kbl++) {
                int kbg = odd * 4 + kbl;
                const unsigned* whr = Wp3 + (kbg * 32 + lane) * WSTR3;
#pragma unroll
                for (int np = 0; np < 4; np++) {
                    uint4 bh = *reinterpret_cast<const uint4*>(whr + np * 4);
                    MMA_F16(a3c[2 * np],     uh[kbl][0], uh[kbl][1], uh[kbl][2], uh[kbl][3], bh.x, bh.y);
                    MMA_F16(a3c[2 * np + 1], uh[kbl][0], uh[kbl][1], uh[kbl][2], uh[kbl][3], bh.z, bh.w);
                }
            }

            // ---- exchange K-split partials for this f ----
            __syncthreads();
            if (odd) {
#pragma unroll
                for (int nb = 0; nb < NB3; nb++) {
                    int col = nb * 8 + cg;
                    *reinterpret_cast<float2*>(&xb[r0 * XSTR + col]) =
                        make_float2(a3c[nb][0], a3c[nb][1]);
                    *reinterpret_cast<float2*>(&xb[r8 * XSTR + col]) =
                        make_float2(a3c[nb][2], a3c[nb][3]);
                }
            }
            __syncthreads();
            if (!odd) {
#pragma unroll
                for (int nb = 0; nb < NB3; nb++) {
                    int col = nb * 8 + cg;
                    float2 x0 = *reinterpret_cast<const float2*>(&xb[r0 * XSTR + col]);
                    float2 x8 = *reinterpret_cast<const float2*>(&xb[r8 * XSTR + col]);
                    *reinterpret_cast<float2*>(&xb[r0 * XSTR + col]) =
                        make_float2(a3c[nb][0] + x0.x, a3c[nb][1] + x0.y);
                    *reinterpret_cast<float2*>(&xb[r8 * XSTR + col]) =
                        make_float2(a3c[nb][2] + x8.x, a3c[nb][3] + x8.y);
                }
            }
        }
        __syncthreads();

        // ---- segment reduction (batch sorted) ----
        {
            int col = tid & 63, chunk = tid >> 6;
            int i0 = chunk * 32, i1 = i0 + 32;
            float sum = 0.f; int cur = -1;
            for (int i = i0; i < i1; i++) {
                int b = sb[i];
                if (b != cur) {
                    if (cur >= 0) atomicAdd(&g_accum[cur * OUTD + col], sum);
                    sum = 0.f; cur = b;
                }
                if (b >= 0) sum += xb[i * XSTR + col];
            }
            if (cur >= 0) atomicAdd(&g_accum[cur * OUTD + col], sum);
        }
        if (tid < 4) {
            int i0 = tid * 32, i1 = i0 + 32;
            float c = 0.f; int cur = -1;
            for (int i = i0; i < i1; i++) {
                int b = sb[i];
                if (b != cur) {
                    if (cur >= 0) atomicAdd(&g_cnt[cur], c);
                    c = 0.f; cur = b;
                }
                if (b >= 0) c += 1.f;
            }
            if (cur >= 0) atomicAdd(&g_cnt[cur], c);
        }
        __syncthreads();
    }
}

__global__ void finalize_kernel(float* __restrict__ out) {
    int idx = blockIdx.x * blockDim.x + threadIdx.x;
    if (idx < NG * OUTD)
        out[idx] = g_accum[idx] / fmaxf(g_cnt[idx >> 6], 1.0f);
}

extern "C" void kernel_launch(void* const* d_in, const int* in_sizes, int n_in,
                              void* d_out, int out_size)
{
    const float* pos   = (const float*)d_in[0];
    const int*   z     = (const int*)  d_in[1];
    const int*   batch = (const int*)  d_in[2];
    const float* emb   = (const float*)d_in[3];
    const float* W1    = (const float*)d_in[4];
    const float* b1    = (const float*)d_in[5];
    const float* W2    = (const float*)d_in[6];
    const float* b2    = (const float*)d_in[7];
    const float* W3    = (const float*)d_in[8];
    const float* b3    = (const float*)d_in[9];

    int N = in_sizes[1];
    int ntiles = (N + MT - 1) / MT;

    size_t smem_bytes = (size_t)(NW2 + NW3) * 4
                      + (size_t)(MT * XSTR) * 4
                      + (size_t)(HID + OUTD) * 4 + 192 * 4
                      + (size_t)(3 * MT) * 4
                      + (size_t)(2 * MT) * 4;
    cudaFuncSetAttribute(gnn_kernel, cudaFuncAttributeMaxDynamicSharedMemorySize,
                         (int)smem_bytes);

    e1_kernel<<<NTYPES, HID>>>(emb, W1, b1);
    permute_w_kernel<<<(KB16 * 32 * 16 * 2 + 255) / 256, 256>>>(W2, W3);
    zero_kernel<<<(NG * OUTD + 255) / 256, 256>>>();

    gnn_kernel<<<GRID_P, NTHREADS, smem_bytes>>>(pos, z, batch, W1, b2, b3, N, ntiles);

    finalize_kernel<<<(NG * OUTD + 255) / 256, 256>>>((float*)d_out);
}

// round 17
// speedup vs baseline: 10.9040x; 1.0950x over previous
#include <cuda_runtime.h>
#include <cuda_fp16.h>

#define NG      4096
#define OUTD    64
#define HID     128
#define NFEAT   125
#define NTYPES  100
#define MT      128
#define NTHREADS 256
#define GRID_P  304
#define KB16    8
#define NB3     8
#define WSTR2   36
#define WSTR3   20
#define NW2     (KB16 * 32 * WSTR2)
#define NW3     (KB16 * 32 * WSTR3)
#define XSTR    66

__device__ float    g_accum[NG * OUTD];
__device__ float    g_cnt[NG];
__device__ unsigned g_E1h[NTYPES * 64];   // E1 rows packed fp16x2
__device__ unsigned g_W2p[NW2];
__device__ unsigned g_W3p[NW3];

__device__ __forceinline__ unsigned pack_f16x2(float lo, float hi) {
    unsigned d;
    asm("cvt.rn.f16x2.f32 %0, %1, %2;" : "=r"(d) : "f"(hi), "f"(lo));
    return d;
}
__device__ __forceinline__ __half2 u2h2(unsigned u) {
    return *reinterpret_cast<const __half2*>(&u);
}
__device__ __forceinline__ unsigned h22u(__half2 h) {
    return *reinterpret_cast<const unsigned*>(&h);
}

#define MMA_F16(c, a0, a1, a2, a3, b0, b1)                                    \
    asm volatile("mma.sync.aligned.m16n8k16.row.col.f32.f16.f16.f32 "         \
                 "{%0,%1,%2,%3},{%4,%5,%6,%7},{%8,%9},{%0,%1,%2,%3};"         \
                 : "+f"(c[0]), "+f"(c[1]), "+f"(c[2]), "+f"(c[3])             \
                 : "r"(a0), "r"(a1), "r"(a2), "r"(a3), "r"(b0), "r"(b1))

__global__ void e1_kernel(const float* __restrict__ emb,
                          const float* __restrict__ W1,
                          const float* __restrict__ b1) {
    __shared__ float e[NFEAT];
    __shared__ float col[HID];
    int t = blockIdx.x, c = threadIdx.x;
    if (c < NFEAT) e[c] = emb[t * NFEAT + c];
    __syncthreads();
    float s = b1[c];
#pragma unroll 5
    for (int d = 0; d < NFEAT; d++)
        s = fmaf(e[d], W1[(3 + d) * HID + c], s);
    col[c] = s;
    __syncthreads();
    if (c < 64)
        g_E1h[t * 64 + c] = pack_f16x2(col[2 * c], col[2 * c + 1]);
}

__global__ void zero_kernel() {
    int idx = blockIdx.x * blockDim.x + threadIdx.x;
    if (idx < NG * OUTD) g_accum[idx] = 0.0f;
    if (idx < NG)        g_cnt[idx]   = 0.0f;
}

__global__ void permute_w_kernel(const float* __restrict__ W2,
                                 const float* __restrict__ W3) {
    int idx = blockIdx.x * blockDim.x + threadIdx.x;
    if (idx < KB16 * 32 * 16 * 2) {
        int j    = idx & 1;
        int nb   = (idx >> 1) % 16;
        int lane = ((idx >> 1) / 16) & 31;
        int kb   = (idx >> 1) / (16 * 32);
        int k0 = kb * 16 + 2 * (lane & 3) + j * 8;
        int n  = nb * 8 + (lane >> 2);
        g_W2p[(kb * 32 + lane) * WSTR2 + nb * 2 + j] =
            pack_f16x2(W2[k0 * HID + n], W2[(k0 + 1) * HID + n]);
    }
    if (idx < KB16 * 32 * NB3 * 2) {
        int j    = idx & 1;
        int nb   = (idx >> 1) % NB3;
        int lane = ((idx >> 1) / NB3) & 31;
        int kb   = (idx >> 1) / (NB3 * 32);
        int k0 = kb * 16 + 2 * (lane & 3) + j * 8;
        int n  = nb * 8 + (lane >> 2);
        g_W3p[(kb * 32 + lane) * WSTR3 + nb * 2 + j] =
            pack_f16x2(W3[k0 * OUTD + n], W3[(k0 + 1) * OUTD + n]);
    }
}

__global__ void __launch_bounds__(NTHREADS, 2) gnn_kernel(
    const float* __restrict__ pos, const int* __restrict__ z,
    const int* __restrict__ batch, const float* __restrict__ W1,
    const float* __restrict__ b2, const float* __restrict__ b3,
    int N, int ntiles)
{
    extern __shared__ unsigned smem[];
    unsigned* Wp2  = smem;                    // NW2
    unsigned* Wp3  = Wp2 + NW2;               // NW3
    float*    xb   = (float*)(Wp3 + NW3);     // MT*XSTR exchange/y
    float*    bs2  = xb + MT * XSTR;          // 128
    float*    bs3  = bs2 + HID;               // 64
    unsigned* w1h  = (unsigned*)(bs3 + OUTD); // 192 fp16x2 (W1 rows 0..2)
    float*    spos = (float*)(w1h + 192);     // 3*MT
    int*      sb   = (int*)(spos + 3 * MT);   // MT
    int*      sz   = sb + MT;                 // MT

    int tid = threadIdx.x, lane = tid & 31, wid = tid >> 5;
    int grp = wid >> 1;
    int odd = wid & 1;
    int cg  = (lane & 3) * 2;

    for (int i = tid; i < NW2 / 4; i += NTHREADS)
        ((uint4*)Wp2)[i] = ((const uint4*)g_W2p)[i];
    for (int i = tid; i < NW3 / 4; i += NTHREADS)
        ((uint4*)Wp3)[i] = ((const uint4*)g_W3p)[i];
    if (tid < 192) {
        int row = tid / 64, c2 = tid % 64;
        w1h[tid] = pack_f16x2(W1[row * HID + 2 * c2], W1[row * HID + 2 * c2 + 1]);
    }
    if (tid < HID)  bs2[tid] = b2[tid];
    if (tid < OUTD) bs3[tid] = b3[tid];
    __syncthreads();

    const __half2 h2z = __float2half2_rn(0.f);

    for (int tile = blockIdx.x; tile < ntiles; tile += gridDim.x) {
        int node0 = tile * MT;
        if (tid < MT) {
            int node = node0 + tid;
            sb[tid] = (node < N) ? batch[node] : -1;
            sz[tid] = (node < N) ? z[node] : 0;
        }
        for (int idx = tid; idx < 3 * MT; idx += NTHREADS) {
            int g = node0 * 3 + idx;
            spos[idx] = (g < N * 3) ? pos[g] : 0.f;
        }
        __syncthreads();

        int rbq = grp * 32 + (lane >> 2);   // f=0 row; f=1 is +16
        const unsigned* e1p[4];
        __half2 pp[4][3];
#pragma unroll
        for (int q = 0; q < 4; q++) {        // q = f*2 + (0:row, 1:row+8)
            int r = rbq + (q >> 1) * 16 + (q & 1) * 8;
            e1p[q] = g_E1h + sz[r] * 64;
            pp[q][0] = __float2half2_rn(spos[3 * r]);
            pp[q][1] = __float2half2_rn(spos[3 * r + 1]);
            pp[q][2] = __float2half2_rn(spos[3 * r + 2]);
        }

        // ---- layer 2 with k-chunked layer-1 fragments, both f per B-load ----
        float acc[2][8][4];
#pragma unroll
        for (int f = 0; f < 2; f++)
#pragma unroll
            for (int nb = 0; nb < 8; nb++) {
                int c = (odd * 8 + nb) * 8 + cg;
                acc[f][nb][0] = bs2[c]; acc[f][nb][1] = bs2[c + 1];
                acc[f][nb][2] = bs2[c]; acc[f][nb][3] = bs2[c + 1];
            }

#pragma unroll
        for (int half = 0; half < 2; half++) {
            // layer-1 chunk: vh[f][kb4][j] for kb = half*4 + kb4
            unsigned vh[2][4][4];
#pragma unroll
            for (int kb4 = 0; kb4 < 4; kb4++) {
#pragma unroll
                for (int jj = 0; jj < 2; jj++) {
                    int c2 = (half * 4 + kb4) * 8 + (lane & 3) + jj * 4;
                    __half2 wa = u2h2(w1h[c2]);
                    __half2 wb = u2h2(w1h[64 + c2]);
                    __half2 wc = u2h2(w1h[128 + c2]);
#pragma unroll
                    for (int f = 0; f < 2; f++) {
                        __half2 vA = __hfma2(pp[2*f][2], wc,
                                     __hfma2(pp[2*f][1], wb,
                                     __hfma2(pp[2*f][0], wa, u2h2(e1p[2*f][c2]))));
                        __half2 vB = __hfma2(pp[2*f+1][2], wc,
                                     __hfma2(pp[2*f+1][1], wb,
                                     __hfma2(pp[2*f+1][0], wa, u2h2(e1p[2*f+1][c2]))));
                        vh[f][kb4][jj * 2]     = h22u(__hmax2(vA, h2z));
                        vh[f][kb4][jj * 2 + 1] = h22u(__hmax2(vB, h2z));
                    }
                }
            }
            // layer-2 partial: B loaded once, feeds both f
#pragma unroll
            for (int kb4 = 0; kb4 < 4; kb4++) {
                int kb = half * 4 + kb4;
                const unsigned* whr = Wp2 + (kb * 32 + lane) * WSTR2 + odd * 16;
#pragma unroll
                for (int np = 0; np < 4; np++) {
                    uint4 bh = *reinterpret_cast<const uint4*>(whr + np * 4);
#pragma unroll
                    for (int f = 0; f < 2; f++) {
                        MMA_F16(acc[f][2 * np],     vh[f][kb4][0], vh[f][kb4][1], vh[f][kb4][2], vh[f][kb4][3], bh.x, bh.y);
                        MMA_F16(acc[f][2 * np + 1], vh[f][kb4][0], vh[f][kb4][1], vh[f][kb4][2], vh[f][kb4][3], bh.z, bh.w);
                    }
                }
            }
        }

        // ---- epilogue l2: relu + pack -> layer3 A fragments ----
        unsigned uh[2][4][4];
#pragma unroll
        for (int f = 0; f < 2; f++)
#pragma unroll
            for (int kbl = 0; kbl < 4; kbl++) {
                uh[f][kbl][0] = pack_f16x2(fmaxf(acc[f][2 * kbl][0], 0.f),
                                           fmaxf(acc[f][2 * kbl][1], 0.f));
                uh[f][kbl][1] = pack_f16x2(fmaxf(acc[f][2 * kbl][2], 0.f),
                                           fmaxf(acc[f][2 * kbl][3], 0.f));
                uh[f][kbl][2] = pack_f16x2(fmaxf(acc[f][2 * kbl + 1][0], 0.f),
                                           fmaxf(acc[f][2 * kbl + 1][1], 0.f));
                uh[f][kbl][3] = pack_f16x2(fmaxf(acc[f][2 * kbl + 1][2], 0.f),
                                           fmaxf(acc[f][2 * kbl + 1][3], 0.f));
            }

        // ---- layer 3 (K-split), both f per B-load ----
        float a3c[2][NB3][4];
#pragma unroll
        for (int f = 0; f < 2; f++)
#pragma unroll
            for (int nb = 0; nb < NB3; nb++) {
                float b0 = odd ? 0.f : bs3[nb * 8 + cg];
                float b1v = odd ? 0.f : bs3[nb * 8 + cg + 1];
                a3c[f][nb][0] = b0; a3c[f][nb][1] = b1v;
                a3c[f][nb][2] = b0; a3c[f][nb][3] = b1v;
            }
#pragma unroll
        for (int kbl = 0; kbl < 4; kbl++) {
            int kbg = odd * 4 + kbl;
            const unsigned* whr = Wp3 + (kbg * 32 + lane) * WSTR3;
#pragma unroll
            for (int np = 0; np < 4; np++) {
                uint4 bh = *reinterpret_cast<const uint4*>(whr + np * 4);
#pragma unroll
                for (int f = 0; f < 2; f++) {
                    MMA_F16(a3c[f][2 * np],     uh[f][kbl][0], uh[f][kbl][1], uh[f][kbl][2], uh[f][kbl][3], bh.x, bh.y);
                    MMA_F16(a3c[f][2 * np + 1], uh[f][kbl][0], uh[f][kbl][1], uh[f][kbl][2], uh[f][kbl][3], bh.z, bh.w);
                }
            }
        }

        // ---- exchange K-split partials (both f, one sync pair) ----
        __syncthreads();
        if (odd) {
#pragma unroll
            for (int f = 0; f < 2; f++) {
                int r0 = rbq + f * 16, r8 = r0 + 8;
#pragma unroll
                for (int nb = 0; nb < NB3; nb++) {
                    int col = nb * 8 + cg;
                    *reinterpret_cast<float2*>(&xb[r0 * XSTR + col]) =
                        make_float2(a3c[f][nb][0], a3c[f][nb][1]);
                    *reinterpret_cast<float2*>(&xb[r8 * XSTR + col]) =
                        make_float2(a3c[f][nb][2], a3c[f][nb][3]);
                }
            }
        }
        __syncthreads();
        if (!odd) {
#pragma unroll
            for (int f = 0; f < 2; f++) {
                int r0 = rbq + f * 16, r8 = r0 + 8;
#pragma unroll
                for (int nb = 0; nb < NB3; nb++) {
                    int col = nb * 8 + cg;
                    float2 x0 = *reinterpret_cast<const float2*>(&xb[r0 * XSTR + col]);
                    float2 x8 = *reinterpret_cast<const float2*>(&xb[r8 * XSTR + col]);
                    *reinterpret_cast<float2*>(&xb[r0 * XSTR + col]) =
                        make_float2(a3c[f][nb][0] + x0.x, a3c[f][nb][1] + x0.y);
                    *reinterpret_cast<float2*>(&xb[r8 * XSTR + col]) =
                        make_float2(a3c[f][nb][2] + x8.x, a3c[f][nb][3] + x8.y);
                }
            }
        }
        __syncthreads();

        // ---- segment reduction (batch sorted) ----
        {
            int col = tid & 63, chunk = tid >> 6;
            int i0 = chunk * 32, i1 = i0 + 32;
            float sum = 0.f; int cur = -1;
            for (int i = i0; i < i1; i++) {
                int b = sb[i];
                if (b != cur) {
                    if (cur >= 0) atomicAdd(&g_accum[cur * OUTD + col], sum);
                    sum = 0.f; cur = b;
                }
                if (b >= 0) sum += xb[i * XSTR + col];
            }
            if (cur >= 0) atomicAdd(&g_accum[cur * OUTD + col], sum);
        }
        if (tid < 4) {
            int i0 = tid * 32, i1 = i0 + 32;
            float c = 0.f; int cur = -1;
            for (int i = i0; i < i1; i++) {
                int b = sb[i];
                if (b != cur) {
                    if (cur >= 0) atomicAdd(&g_cnt[cur], c);
                    c = 0.f; cur = b;
                }
                if (b >= 0) c += 1.f;
            }
            if (cur >= 0) atomicAdd(&g_cnt[cur], c);
        }
        __syncthreads();
    }
}

__global__ void finalize_kernel(float* __restrict__ out) {
    int idx = blockIdx.x * blockDim.x + threadIdx.x;
    if (idx < NG * OUTD)
        out[idx] = g_accum[idx] / fmaxf(g_cnt[idx >> 6], 1.0f);
}

extern "C" void kernel_launch(void* const* d_in, const int* in_sizes, int n_in,
                              void* d_out, int out_size)
{
    const float* pos   = (const float*)d_in[0];
    const int*   z     = (const int*)  d_in[1];
    const int*   batch = (const int*)  d_in[2];
    const float* emb   = (const float*)d_in[3];
    const float* W1    = (const float*)d_in[4];
    const float* b1    = (const float*)d_in[5];
    const float* W2    = (const float*)d_in[6];
    const float* b2    = (const float*)d_in[7];
    const float* W3    = (const float*)d_in[8];
    const float* b3    = (const float*)d_in[9];

    int N = in_sizes[1];
    int ntiles = (N + MT - 1) / MT;

    size_t smem_bytes = (size_t)(NW2 + NW3) * 4
                      + (size_t)(MT * XSTR) * 4
                      + (size_t)(HID + OUTD) * 4 + 192 * 4
                      + (size_t)(3 * MT) * 4
                      + (size_t)(2 * MT) * 4;
    cudaFuncSetAttribute(gnn_kernel, cudaFuncAttributeMaxDynamicSharedMemorySize,
                         (int)smem_bytes);

    e1_kernel<<<NTYPES, HID>>>(emb, W1, b1);
    permute_w_kernel<<<(KB16 * 32 * 16 * 2 + 255) / 256, 256>>>(W2, W3);
    zero_kernel<<<(NG * OUTD + 255) / 256, 256>>>();

    gnn_kernel<<<GRID_P, NTHREADS, smem_bytes>>>(pos, z, batch, W1, b2, b3, N, ntiles);

    finalize_kernel<<<(NG * OUTD + 255) / 256, 256>>>((float*)d_out);
}